// round 14
// baseline (speedup 1.0000x reference)
#include <cuda_runtime.h>
#include <cuda_bf16.h>
#include <cuda_fp16.h>
#include <math.h>
#include <stdint.h>

#define Bb   2
#define Tt   2048
#define Vv   32000
#define Dd   1024
#define Ff   256
#define NLl  6
#define LATl 64
#define Mrows (Bb*Tt)

// ===== fp32 scratch =====
__device__ __align__(128) float g_h[Mrows*Dd];
__device__ __align__(128) float g_xn[Mrows*Dd];
__device__ __align__(128) float g_buf1[Mrows*4*Dd];
__device__ __align__(128) float g_concept[Mrows*Dd];
__device__ __align__(128) float g_sp[Mrows*2*Ff];
__device__ __align__(128) float g_decay[Mrows*Ff];
__device__ __align__(128) float g_params[Mrows*2*LATl];
__device__ float g_accum;

// ===== fp16 weights: [hi | lo] layout, row length 2K =====
__device__ __align__(1024) __half w_gate2[(size_t)NLl*Dd*2*Dd];
__device__ __align__(1024) __half w_ogate2[(size_t)NLl*Dd*2*Dd];
__device__ __align__(1024) __half w_decay2[(size_t)NLl*Ff*2*Dd];
__device__ __align__(1024) __half w_si2[(size_t)NLl*2*Ff*2*Dd];
__device__ __align__(1024) __half w_so2[(size_t)NLl*Dd*2*2*Ff];
__device__ __align__(1024) __half w_f12[(size_t)NLl*4*Dd*2*Dd];
__device__ __align__(1024) __half w_f22[(size_t)NLl*Dd*2*4*Dd];
__device__ __align__(1024) __half w_enc2[2*LATl*2*Dd];
__device__ __align__(1024) __half w_dec2[Dd*2*LATl];
__device__ __align__(1024) __half w_emb2[(size_t)Vv*2*Dd];
// fp16 activations (plain hi)
__device__ __align__(1024) __half a_xnh[(size_t)Mrows*Dd];
__device__ __align__(1024) __half a_uh[(size_t)Mrows*Dd];
__device__ __align__(1024) __half a_fh[(size_t)Mrows*4*Dd];
__device__ __align__(1024) __half a_yc[(size_t)Mrows*2*Ff];
__device__ __align__(1024) __half a_muh[(size_t)Mrows*LATl];

// ===== helpers =====
__inline__ __device__ float warpsum(float v) {
#pragma unroll
    for (int o = 16; o > 0; o >>= 1) v += __shfl_xor_sync(0xffffffffu, v, o);
    return v;
}
__device__ __forceinline__ uint32_t smem_u32(const void* p) {
    uint32_t a;
    asm("{ .reg .u64 t; cvta.to.shared.u64 t, %1; cvt.u32.u64 %0, t; }" : "=r"(a) : "l"(p));
    return a;
}
__device__ __forceinline__ void cp16(uint32_t dst, const void* src) {
    asm volatile("cp.async.cg.shared.global [%0], [%1], 16;" :: "r"(dst), "l"(src));
}
__device__ __forceinline__ void cp_commit() { asm volatile("cp.async.commit_group;" ::: "memory"); }
__device__ __forceinline__ void ldm_x4(uint32_t& r0, uint32_t& r1, uint32_t& r2, uint32_t& r3, uint32_t addr) {
    asm volatile("ldmatrix.sync.aligned.m8n8.x4.shared.b16 {%0,%1,%2,%3}, [%4];"
                 : "=r"(r0), "=r"(r1), "=r"(r2), "=r"(r3) : "r"(addr));
}
__device__ __forceinline__ void mma_f16(float* c, const uint32_t* a, const uint32_t* b) {
    asm volatile("mma.sync.aligned.m16n8k16.row.col.f32.f16.f16.f32 "
                 "{%0,%1,%2,%3}, {%4,%5,%6,%7}, {%8,%9}, {%0,%1,%2,%3};"
                 : "+f"(c[0]), "+f"(c[1]), "+f"(c[2]), "+f"(c[3])
                 : "r"(a[0]), "r"(a[1]), "r"(a[2]), "r"(a[3]), "r"(b[0]), "r"(b[1]));
}

// ===== weight split =====
__global__ void split2_f16_kernel(const float* __restrict__ in, __half* __restrict__ out,
                                  long n, int K) {
    long i = (long)blockIdx.x * blockDim.x + threadIdx.x;
    if (i >= n) return;
    long m = i / K; int k = (int)(i - m * K);
    float x = in[i];
    __half hi = __float2half_rn(x);
    __half lo = __float2half_rn(x - __half2float(hi));
    long ob = m * (long)(2 * K);
    out[ob + k] = hi; out[ob + K + k] = lo;
}
__global__ void cvt_mu_kernel() {
    int i = blockIdx.x * blockDim.x + threadIdx.x;
    if (i >= Mrows * LATl) return;
    int m = i >> 6, l = i & 63;
    a_muh[i] = __float2half_rn(g_params[(size_t)m * (2 * LATl) + l]);
}

// ===== HMMA GEMM =====
// C[m,n] (=|+=) (mul?mul:1)*act(sum_{k<K} A[m,mapA(k)]B[n,mapB(k)] + bias[n])
// NT: BN = 128*NT, warp tile 64 x (32*NT). 8 warps (2 m x 4 n). BK=32, 3-stage cp.async.
#define ROWB 80
#define NSTG 3

template<int NT>
__global__ void __launch_bounds__(256, 1) gemm_mma(
    const __half* __restrict__ A, const __half* __restrict__ B,
    const float* __restrict__ bias, float* __restrict__ C,
    const float* __restrict__ mul, __half* __restrict__ Csplit,
    int N, int K, int ldA, int ldB, int limA, int subA,
    int act, int addC)
{
    constexpr int BN = 128 * NT;
    constexpr int WN = 32 * NT;              // cols per warp
    constexpr int TBA = 128 * ROWB;
    constexpr int TBB = BN * ROWB;
    constexpr int STGB = TBA + TBB;

    extern __shared__ char dsm[];
    const uint32_t sm = smem_u32(dsm);
    const int tid = threadIdx.x;
    const int wid = tid >> 5, lane = tid & 31;
    const int warp_m = wid >> 2;             // 0..1
    const int warp_n = wid & 3;              // 0..3
    const int rowBase = blockIdx.x * 128;
    const int colBase = blockIdx.y * BN;
    const int NC = K >> 5;

    float acc[4][WN / 8][4];
#pragma unroll
    for (int i = 0; i < 4; i++)
#pragma unroll
        for (int j = 0; j < WN / 8; j++)
#pragma unroll
            for (int q = 0; q < 4; q++) acc[i][j][q] = 0.f;

    auto loadTile = [&](int it, int stg) {
        const int k0 = it * 32;
        const int kA = k0 >= limA ? k0 - subA : k0;
        const uint32_t sbase = sm + stg * STGB;
#pragma unroll
        for (int i = 0; i < 2; i++) {
            int c = tid + i * 256;
            int r = c >> 2, ch = c & 3;
            cp16(sbase + r * ROWB + ch * 16,
                 A + (size_t)(rowBase + r) * ldA + kA + ch * 8);
        }
#pragma unroll
        for (int i = 0; i < BN / 64; i++) {
            int c = tid + i * 256;
            int r = c >> 2, ch = c & 3;
            cp16(sbase + TBA + r * ROWB + ch * 16,
                 B + (size_t)(colBase + r) * ldB + k0 + ch * 8);
        }
    };

    const uint32_t aOff = (uint32_t)((warp_m * 64 + (lane & 15)) * ROWB + (lane >> 4) * 16);
    const uint32_t bOff = (uint32_t)(TBA +
        (warp_n * WN + (lane & 7) + ((lane >> 4) & 1) * 8) * ROWB + ((lane >> 3) & 1) * 16);

    loadTile(0, 0); cp_commit();
    loadTile(1, 1); cp_commit();

    for (int it = 0; it < NC; it++) {
        asm volatile("cp.async.wait_group 1;" ::: "memory");
        __syncthreads();
        if (it + 2 < NC) loadTile(it + 2, (it + 2) % NSTG);
        cp_commit();

        const uint32_t sbase = sm + (it % NSTG) * STGB;
#pragma unroll
        for (int ks = 0; ks < 2; ks++) {
            uint32_t a[4][4];
#pragma unroll
            for (int mt = 0; mt < 4; mt++)
                ldm_x4(a[mt][0], a[mt][1], a[mt][2], a[mt][3],
                       sbase + aOff + mt * (16 * ROWB) + ks * 32);
            uint32_t bf[WN / 8][2];
#pragma unroll
            for (int np = 0; np < WN / 16; np++) {
                uint32_t r0, r1, r2, r3;
                ldm_x4(r0, r1, r2, r3, sbase + bOff + np * (16 * ROWB) + ks * 32);
                bf[np * 2][0] = r0; bf[np * 2][1] = r1;
                bf[np * 2 + 1][0] = r2; bf[np * 2 + 1][1] = r3;
            }
#pragma unroll
            for (int mt = 0; mt < 4; mt++)
#pragma unroll
                for (int nt = 0; nt < WN / 8; nt++)
                    mma_f16(acc[mt][nt], a[mt], bf[nt]);
        }
    }

    const int gid = lane >> 2, tig = lane & 3;
#pragma unroll
    for (int mt = 0; mt < 4; mt++) {
#pragma unroll
        for (int nt = 0; nt < WN / 8; nt++) {
            int c = colBase + warp_n * WN + nt * 8 + tig * 2;
            float bv0 = 0.f, bv1 = 0.f;
            if (bias) { bv0 = bias[c]; bv1 = bias[c + 1]; }
#pragma unroll
            for (int half = 0; half < 2; half++) {
                int r = rowBase + warp_m * 64 + mt * 16 + gid + half * 8;
                float v0 = acc[mt][nt][half * 2 + 0] + bv0;
                float v1 = acc[mt][nt][half * 2 + 1] + bv1;
                if (act == 1) {
                    v0 = 1.0f / (1.0f + expf(-v0));
                    v1 = 1.0f / (1.0f + expf(-v1));
                } else if (act == 2) {
                    v0 = 0.5f * v0 * (1.0f + erff(v0 * 0.70710678118654752f));
                    v1 = 0.5f * v1 * (1.0f + erff(v1 * 0.70710678118654752f));
                }
                size_t ix = (size_t)r * N + c;
                if (mul) {
                    float2 mm = *(const float2*)(mul + ix);
                    v0 *= mm.x; v1 *= mm.y;
                }
                if (C) {
                    float a0 = v0, a1 = v1;
                    if (addC) {
                        float2 o = *(const float2*)(C + ix);
                        a0 += o.x; a1 += o.y;
                    }
                    float2 w; w.x = a0; w.y = a1;
                    *(float2*)(C + ix) = w;
                }
                if (Csplit) {
                    *reinterpret_cast<__half2*>(Csplit + ix) = __floats2half2_rn(v0, v1);
                }
            }
        }
    }
}

// ===== misc kernels =====
__global__ void embed_kernel(const int* __restrict__ x, const float* __restrict__ emb) {
    int row = blockIdx.x;
    int tok = x[row];
    size_t src = (size_t)tok * Dd, dst = (size_t)row * Dd;
#pragma unroll
    for (int i = 0; i < 4; i++) {
        int c = threadIdx.x + i * 256;
        g_h[dst + c] = emb[src + c];
    }
}

__global__ void __launch_bounds__(256) layernorm_kernel(
    const float* __restrict__ in, const float* __restrict__ in2,
    const float* __restrict__ g, const float* __restrict__ bb,
    float* __restrict__ out, __half* __restrict__ outh)
{
    int row = blockIdx.x;
    size_t base = (size_t)row * Dd;
    float vals[4];
    float s = 0.f, s2 = 0.f;
#pragma unroll
    for (int i = 0; i < 4; i++) {
        int c = threadIdx.x + i * 256;
        float v = in[base + c];
        if (in2) v += in2[base + c];
        vals[i] = v; s += v; s2 += v * v;
    }
    __shared__ float sh1[8], sh2[8];
    s = warpsum(s); s2 = warpsum(s2);
    int w = threadIdx.x >> 5, l = threadIdx.x & 31;
    if (l == 0) { sh1[w] = s; sh2[w] = s2; }
    __syncthreads();
    if (w == 0) {
        float a = (l < 8) ? sh1[l] : 0.f;
        float b2 = (l < 8) ? sh2[l] : 0.f;
        a = warpsum(a); b2 = warpsum(b2);
        if (l == 0) { sh1[0] = a; sh2[0] = b2; }
    }
    __syncthreads();
    float mean = sh1[0] * (1.f / Dd);
    float inv = rsqrtf(sh2[0] * (1.f / Dd) - mean * mean + 1e-5f);
#pragma unroll
    for (int i = 0; i < 4; i++) {
        int c = threadIdx.x + i * 256;
        float v = (vals[i] - mean) * inv * g[c] + bb[c];
        if (out) out[base + c] = v;
        if (outh) outh[base + c] = __float2half_rn(v);
    }
}

// warp-parallel complex scan; writes fp16 ycat directly.
__global__ void __launch_bounds__(256) scan2_kernel(const float* __restrict__ freq) {
    int gwarp = (blockIdx.x * blockDim.x + threadIdx.x) >> 5;
    int lane = threadIdx.x & 31;
    if (gwarp >= Bb * Ff) return;
    int b = gwarp >> 8, f = gwarp & 255;
    float w = 0.1f * freq[f];
    float cw = cosf(w), sw = sinf(w);
    const int L = Tt / 32;
    size_t rbase = (size_t)b * Tt + (size_t)lane * L;

    float Ar = 1.f, Ai = 0.f, Ur = 0.f, Ui = 0.f;
    for (int s = 0; s < L; s++) {
        size_t row = rbase + s;
        float dcy = g_decay[row * Ff + f];
        float ur = g_sp[row * (2 * Ff) + f];
        float ui = g_sp[row * (2 * Ff) + Ff + f];
        float ar = dcy * cw, ai = dcy * sw;
        float nAr = ar * Ar - ai * Ai, nAi = ar * Ai + ai * Ar;
        float nUr = ar * Ur - ai * Ui + ur, nUi = ar * Ui + ai * Ur + ui;
        Ar = nAr; Ai = nAi; Ur = nUr; Ui = nUi;
    }
#pragma unroll
    for (int off = 1; off < 32; off <<= 1) {
        float pAr = __shfl_up_sync(0xffffffffu, Ar, off);
        float pAi = __shfl_up_sync(0xffffffffu, Ai, off);
        float pUr = __shfl_up_sync(0xffffffffu, Ur, off);
        float pUi = __shfl_up_sync(0xffffffffu, Ui, off);
        if (lane >= off) {
            float nAr = Ar * pAr - Ai * pAi;
            float nAi = Ar * pAi + Ai * pAr;
            float nUr = Ar * pUr - Ai * pUi + Ur;
            float nUi = Ar * pUi + Ai * pUr + Ui;
            Ar = nAr; Ai = nAi; Ur = nUr; Ui = nUi;
        }
    }
    float Pr = __shfl_up_sync(0xffffffffu, Ur, 1);
    float Pi = __shfl_up_sync(0xffffffffu, Ui, 1);
    if (lane == 0) { Pr = 0.f; Pi = 0.f; }

    float yr = Pr, yi = Pi;
    for (int s = 0; s < L; s++) {
        size_t row = rbase + s;
        float dcy = g_decay[row * Ff + f];
        float ur = g_sp[row * (2 * Ff) + f];
        float ui = g_sp[row * (2 * Ff) + Ff + f];
        float ar = dcy * cw, ai = dcy * sw;
        float nyr = ar * yr - ai * yi + ur;
        float nyi = ar * yi + ai * yr + ui;
        yr = nyr; yi = nyi;
        a_yc[row * (2 * Ff) + f] = __float2half_rn(yr);
        a_yc[row * (2 * Ff) + Ff + f] = __float2half_rn(yi);
    }
}

__global__ void kl_zero_kernel() { g_accum = 0.f; }
__global__ void __launch_bounds__(256) kl_reduce_kernel() {
    int i = blockIdx.x * blockDim.x + threadIdx.x;
    float v = 0.f;
    if (i < Mrows * LATl) {
        int row = i / LATl, l = i % LATl;
        float mu = g_params[(size_t)row * (2 * LATl) + l];
        float lv = g_params[(size_t)row * (2 * LATl) + LATl + l];
        v = -0.5f * (1.f + lv - mu * mu - expf(lv));
    }
    v = warpsum(v);
    __shared__ float sh[8];
    int w = threadIdx.x >> 5, l = threadIdx.x & 31;
    if (l == 0) sh[w] = v;
    __syncthreads();
    if (w == 0) {
        float a = (l < 8) ? sh[l] : 0.f;
        a = warpsum(a);
        if (l == 0) atomicAdd(&g_accum, a);
    }
}
__global__ void kl_final_kernel(float* __restrict__ out, int do_write) {
    if (do_write) out[0] = 0.01f * fmaxf(g_accum * (1.f / (float)(Mrows * LATl)), 0.05f);
}

// ===== host =====
#define SMEM1 (NSTG * (128 * ROWB + 128 * ROWB))
#define SMEM2 (NSTG * (128 * ROWB + 256 * ROWB))

static void wsplit_f16(const float* in, __half* out, long rows, int K) {
    long n = rows * K;
    split2_f16_kernel<<<(unsigned)((n + 255) / 256), 256>>>(in, out, n, K);
}
// fp16 2-term: A plain [rows x Ka], B [hi|lo] (2Ka); K' = 2Ka
static void gemm_f16(const __half* A, const __half* B, const float* bias, float* C,
                     const float* mul, __half* Csplit, int N, int Ka, int act, int addC) {
    if (N % 256 == 0) {
        dim3 grid(Mrows / 128, N / 256);
        gemm_mma<2><<<grid, 256, SMEM2>>>(A, B, bias, C, mul, Csplit,
            N, 2 * Ka, Ka, 2 * Ka, Ka, Ka, act, addC);
    } else {
        dim3 grid(Mrows / 128, N / 128);
        gemm_mma<1><<<grid, 256, SMEM1>>>(A, B, bias, C, mul, Csplit,
            N, 2 * Ka, Ka, 2 * Ka, Ka, Ka, act, addC);
    }
}

extern "C" void kernel_launch(void* const* d_in, const int* in_sizes, int n_in,
                              void* d_out, int out_size) {
    (void)in_sizes; (void)n_in;
    const int*   x         = (const int*)  d_in[0];
    const float* emb       = (const float*)d_in[1];
    const float* freq      = (const float*)d_in[2];
    const float* decay_W   = (const float*)d_in[3];
    const float* decay_b   = (const float*)d_in[4];
    const float* spec_in_W = (const float*)d_in[5];
    const float* spec_out_W= (const float*)d_in[6];
    const float* norm1_g   = (const float*)d_in[7];
    const float* norm1_b   = (const float*)d_in[8];
    const float* gate_W    = (const float*)d_in[9];
    const float* gate_b    = (const float*)d_in[10];
    const float* ogate_W   = (const float*)d_in[11];
    const float* ogate_b   = (const float*)d_in[12];
    const float* ffn_g     = (const float*)d_in[13];
    const float* ffn_b     = (const float*)d_in[14];
    const float* ffn_W1    = (const float*)d_in[15];
    const float* ffn_b1    = (const float*)d_in[16];
    const float* ffn_W2    = (const float*)d_in[17];
    const float* ffn_b2    = (const float*)d_in[18];
    const float* vib_g     = (const float*)d_in[19];
    const float* vib_b     = (const float*)d_in[20];
    const float* enc_W     = (const float*)d_in[21];
    const float* enc_b     = (const float*)d_in[22];
    const float* dec_W     = (const float*)d_in[23];
    const float* dec_b     = (const float*)d_in[24];
    const float* normf_g   = (const float*)d_in[25];
    const float* normf_b   = (const float*)d_in[26];
    float* logits = (float*)d_out;

    cudaFuncSetAttribute((const void*)gemm_mma<1>,
                         cudaFuncAttributeMaxDynamicSharedMemorySize, SMEM1);
    cudaFuncSetAttribute((const void*)gemm_mma<2>,
                         cudaFuncAttributeMaxDynamicSharedMemorySize, SMEM2);

    float *p_h, *p_xn, *p_buf1, *p_concept, *p_sp, *p_decay, *p_params;
    cudaGetSymbolAddress((void**)&p_h, g_h);
    cudaGetSymbolAddress((void**)&p_xn, g_xn);
    cudaGetSymbolAddress((void**)&p_buf1, g_buf1);
    cudaGetSymbolAddress((void**)&p_concept, g_concept);
    cudaGetSymbolAddress((void**)&p_sp, g_sp);
    cudaGetSymbolAddress((void**)&p_decay, g_decay);
    cudaGetSymbolAddress((void**)&p_params, g_params);

    __half *pw_gate, *pw_ogate, *pw_decay, *pw_si, *pw_so, *pw_f1, *pw_f2, *pw_enc, *pw_dec, *pw_emb;
    __half *pa_xnh, *pa_uh, *pa_fh, *pa_muh, *pa_yc;
    cudaGetSymbolAddress((void**)&pw_gate, w_gate2);
    cudaGetSymbolAddress((void**)&pw_ogate, w_ogate2);
    cudaGetSymbolAddress((void**)&pw_decay, w_decay2);
    cudaGetSymbolAddress((void**)&pw_si, w_si2);
    cudaGetSymbolAddress((void**)&pw_so, w_so2);
    cudaGetSymbolAddress((void**)&pw_f1, w_f12);
    cudaGetSymbolAddress((void**)&pw_f2, w_f22);
    cudaGetSymbolAddress((void**)&pw_enc, w_enc2);
    cudaGetSymbolAddress((void**)&pw_dec, w_dec2);
    cudaGetSymbolAddress((void**)&pw_emb, w_emb2);
    cudaGetSymbolAddress((void**)&pa_xnh, a_xnh);
    cudaGetSymbolAddress((void**)&pa_uh, a_uh);
    cudaGetSymbolAddress((void**)&pa_fh, a_fh);
    cudaGetSymbolAddress((void**)&pa_muh, a_muh);
    cudaGetSymbolAddress((void**)&pa_yc, a_yc);

    // launches 0-2 feed layer-0 gate GEMM (launch 5 = ncu -s 5 target)
    wsplit_f16(emb, pw_emb, Vv, Dd);                        // 0
    wsplit_f16(gate_W, pw_gate, (long)NLl * Dd, Dd);        // 1
    wsplit_f16(ogate_W, pw_ogate, (long)NLl * Dd, Dd);      // 2
    embed_kernel<<<Mrows, 256>>>(x, emb);                   // 3
    layernorm_kernel<<<Mrows, 256>>>(p_h, nullptr, norm1_g, norm1_b, p_xn, pa_xnh); // 4
    gemm_f16(pa_xnh, pw_gate, gate_b, nullptr, p_xn, pa_uh, Dd, Dd, 1, 0);          // 5

    wsplit_f16(decay_W, pw_decay, (long)NLl * Ff, Dd);
    wsplit_f16(spec_in_W, pw_si, (long)NLl * 2 * Ff, Dd);
    wsplit_f16(spec_out_W, pw_so, (long)NLl * Dd, 2 * Ff);
    wsplit_f16(ffn_W1, pw_f1, (long)NLl * 4 * Dd, Dd);
    wsplit_f16(ffn_W2, pw_f2, (long)NLl * Dd, 4 * Dd);
    wsplit_f16(enc_W, pw_enc, 2 * LATl, Dd);
    wsplit_f16(dec_W, pw_dec, Dd, LATl);

    for (int i = 0; i < NLl; i++) {
        const __half* gW = pw_gate + (size_t)i * Dd * 2 * Dd;
        const __half* oW = pw_ogate + (size_t)i * Dd * 2 * Dd;
        const __half* dW = pw_decay + (size_t)i * Ff * 2 * Dd;
        const __half* siW = pw_si + (size_t)i * 2 * Ff * 2 * Dd;
        const __half* soW = pw_so + (size_t)i * Dd * 2 * 2 * Ff;
        const __half* w1 = pw_f1 + (size_t)i * 4 * Dd * 2 * Dd;
        const __half* w2 = pw_f2 + (size_t)i * Dd * 2 * 4 * Dd;

        if (i > 0) {
            layernorm_kernel<<<Mrows, 256>>>(p_h, nullptr, norm1_g + i * Dd, norm1_b + i * Dd, p_xn, pa_xnh);
            gemm_f16(pa_xnh, gW, gate_b + i * Dd, nullptr, p_xn, pa_uh, Dd, Dd, 1, 0);
        }
        gemm_f16(pa_uh, dW, decay_b + i * Ff, p_decay, nullptr, nullptr, Ff, Dd, 1, 0);
        gemm_f16(pa_uh, siW, nullptr, p_sp, nullptr, nullptr, 2 * Ff, Dd, 0, 0);
        scan2_kernel<<<Bb * Ff * 32 / 256, 256>>>(freq + i * Ff);
        gemm_f16(pa_xnh, oW, ogate_b + i * Dd, p_buf1, nullptr, nullptr, Dd, Dd, 1, 0);
        gemm_f16(pa_yc, soW, nullptr, p_h, p_buf1, nullptr, Dd, 2 * Ff, 0, 1);
        layernorm_kernel<<<Mrows, 256>>>(p_h, nullptr, ffn_g + i * Dd, ffn_b + i * Dd, p_xn, pa_xnh);
        gemm_f16(pa_xnh, w1, ffn_b1 + i * 4 * Dd, nullptr, nullptr, pa_fh, 4 * Dd, Dd, 2, 0);
        gemm_f16(pa_fh, w2, ffn_b2 + i * Dd, p_h, nullptr, nullptr, Dd, 4 * Dd, 0, 1);
    }

    // VIB head
    layernorm_kernel<<<Mrows, 256>>>(p_h, nullptr, vib_g, vib_b, p_xn, pa_xnh);
    gemm_f16(pa_xnh, pw_enc, enc_b, p_params, nullptr, nullptr, 2 * LATl, Dd, 0, 0);
    cvt_mu_kernel<<<(Mrows * LATl + 255) / 256, 256>>>();
    gemm_f16(pa_muh, pw_dec, dec_b, p_concept, nullptr, nullptr, Dd, LATl, 2, 0);
    layernorm_kernel<<<Mrows, 256>>>(p_h, p_concept, normf_g, normf_b, nullptr, pa_xnh);
    gemm_f16(pa_xnh, pw_emb, nullptr, logits, nullptr, nullptr, Vv, Dd, 0, 0);

    kl_zero_kernel<<<1, 1>>>();
    kl_reduce_kernel<<<(Mrows * LATl + 255) / 256, 256>>>();
    int do_write = (out_size >= Mrows * Vv + 1) ? 1 : 0;
    kl_final_kernel<<<1, 1>>>(logits + (size_t)Mrows * Vv, do_write);
}

// round 15
// speedup vs baseline: 1.0460x; 1.0460x over previous
#include <cuda_runtime.h>
#include <cuda_bf16.h>
#include <cuda_fp16.h>
#include <math.h>
#include <stdint.h>

#define Bb   2
#define Tt   2048
#define Vv   32000
#define Dd   1024
#define Ff   256
#define NLl  6
#define LATl 64
#define Mrows (Bb*Tt)

// ===== fp32 scratch =====
__device__ __align__(128) float g_h[Mrows*Dd];
__device__ __align__(128) float g_xn[Mrows*Dd];
__device__ __align__(128) float g_buf1[Mrows*4*Dd];
__device__ __align__(128) float g_concept[Mrows*Dd];
__device__ __align__(128) float g_sp[Mrows*2*Ff];
__device__ __align__(128) float g_decay[Mrows*Ff];
__device__ __align__(128) float g_params[Mrows*2*LATl];
__device__ float g_accum;

// ===== fp16 weights: [hi | lo] layout, row length 2K =====
__device__ __align__(1024) __half w_gate2[(size_t)NLl*Dd*2*Dd];
__device__ __align__(1024) __half w_ogate2[(size_t)NLl*Dd*2*Dd];
__device__ __align__(1024) __half w_decay2[(size_t)NLl*Ff*2*Dd];
__device__ __align__(1024) __half w_si2[(size_t)NLl*2*Ff*2*Dd];
__device__ __align__(1024) __half w_so2[(size_t)NLl*Dd*2*2*Ff];
__device__ __align__(1024) __half w_f12[(size_t)NLl*4*Dd*2*Dd];
__device__ __align__(1024) __half w_f22[(size_t)NLl*Dd*2*4*Dd];
__device__ __align__(1024) __half w_enc2[2*LATl*2*Dd];
__device__ __align__(1024) __half w_dec2[Dd*2*LATl];
__device__ __align__(1024) __half w_emb2[(size_t)Vv*2*Dd];
// fp16 activations (plain hi)
__device__ __align__(1024) __half a_xnh[(size_t)Mrows*Dd];
__device__ __align__(1024) __half a_uh[(size_t)Mrows*Dd];
__device__ __align__(1024) __half a_fh[(size_t)Mrows*4*Dd];
__device__ __align__(1024) __half a_yc[(size_t)Mrows*2*Ff];
__device__ __align__(1024) __half a_muh[(size_t)Mrows*LATl];

// ===== helpers =====
__inline__ __device__ float warpsum(float v) {
#pragma unroll
    for (int o = 16; o > 0; o >>= 1) v += __shfl_xor_sync(0xffffffffu, v, o);
    return v;
}
__device__ __forceinline__ uint32_t smem_u32(const void* p) {
    uint32_t a;
    asm("{ .reg .u64 t; cvta.to.shared.u64 t, %1; cvt.u32.u64 %0, t; }" : "=r"(a) : "l"(p));
    return a;
}
__device__ __forceinline__ void cp16(uint32_t dst, const void* src) {
    asm volatile("cp.async.cg.shared.global [%0], [%1], 16;" :: "r"(dst), "l"(src));
}
__device__ __forceinline__ void cp_commit() { asm volatile("cp.async.commit_group;" ::: "memory"); }
__device__ __forceinline__ void ldm_x4(uint32_t& r0, uint32_t& r1, uint32_t& r2, uint32_t& r3, uint32_t addr) {
    asm volatile("ldmatrix.sync.aligned.m8n8.x4.shared.b16 {%0,%1,%2,%3}, [%4];"
                 : "=r"(r0), "=r"(r1), "=r"(r2), "=r"(r3) : "r"(addr));
}
__device__ __forceinline__ void mma_f16(float* c, const uint32_t* a, const uint32_t* b) {
    asm volatile("mma.sync.aligned.m16n8k16.row.col.f32.f16.f16.f32 "
                 "{%0,%1,%2,%3}, {%4,%5,%6,%7}, {%8,%9}, {%0,%1,%2,%3};"
                 : "+f"(c[0]), "+f"(c[1]), "+f"(c[2]), "+f"(c[3])
                 : "r"(a[0]), "r"(a[1]), "r"(a[2]), "r"(a[3]), "r"(b[0]), "r"(b[1]));
}
__device__ __forceinline__ float epi_act(float v, int act) {
    if (act == 1) return 1.0f / (1.0f + expf(-v));
    if (act == 2) return 0.5f * v * (1.0f + erff(v * 0.70710678118654752f));
    return v;
}

// ===== weight split =====
__global__ void split2_f16_kernel(const float* __restrict__ in, __half* __restrict__ out,
                                  long n, int K) {
    long i = (long)blockIdx.x * blockDim.x + threadIdx.x;
    if (i >= n) return;
    long m = i / K; int k = (int)(i - m * K);
    float x = in[i];
    __half hi = __float2half_rn(x);
    __half lo = __float2half_rn(x - __half2float(hi));
    long ob = m * (long)(2 * K);
    out[ob + k] = hi; out[ob + K + k] = lo;
}
__global__ void cvt_mu_kernel() {
    int i = blockIdx.x * blockDim.x + threadIdx.x;
    if (i >= Mrows * LATl) return;
    int m = i >> 6, l = i & 63;
    a_muh[i] = __float2half_rn(g_params[(size_t)m * (2 * LATl) + l]);
}

#define ROWB 80
#define NSTG 3

// ===== shared epilogue macro body (per 16x8 fragment) =====
// ===== GEMM kernel: BM x 128 CTA tile. BM=128: 256 thr (2x4 warps). BM=64: 128 thr (1x4 warps).
template<int BM>
__global__ void __launch_bounds__(BM == 128 ? 256 : 128, BM == 128 ? 1 : 4) gemm_mma(
    const __half* __restrict__ A, const __half* __restrict__ B,
    const float* __restrict__ bias, float* __restrict__ C,
    const float* __restrict__ mul, __half* __restrict__ Csplit,
    int N, int K, int ldA, int ldB, int limA, int subA,
    int act, int addC)
{
    constexpr int NTHR = (BM == 128) ? 256 : 128;
    constexpr int TBA = BM * ROWB;
    constexpr int TBB = 128 * ROWB;
    constexpr int STGB = TBA + TBB;

    extern __shared__ char dsm[];
    const uint32_t sm = smem_u32(dsm);
    const int tid = threadIdx.x;
    const int wid = tid >> 5, lane = tid & 31;
    const int warp_m = (BM == 128) ? (wid >> 2) : 0;
    const int warp_n = wid & 3;
    const int rowBase = blockIdx.x * BM;
    const int colBase = blockIdx.y * 128;
    const int NC = K >> 5;

    float acc[4][4][4];
#pragma unroll
    for (int i = 0; i < 4; i++)
#pragma unroll
        for (int j = 0; j < 4; j++)
#pragma unroll
            for (int q = 0; q < 4; q++) acc[i][j][q] = 0.f;

    auto loadTile = [&](int it, int stg) {
        const int k0 = it * 32;
        const int kA = k0 >= limA ? k0 - subA : k0;
        const uint32_t sbase = sm + stg * STGB;
#pragma unroll
        for (int i = 0; i < BM * 4 / NTHR; i++) {
            int c = tid + i * NTHR;
            int r = c >> 2, ch = c & 3;
            cp16(sbase + r * ROWB + ch * 16,
                 A + (size_t)(rowBase + r) * ldA + kA + ch * 8);
        }
#pragma unroll
        for (int i = 0; i < 512 / NTHR; i++) {
            int c = tid + i * NTHR;
            int r = c >> 2, ch = c & 3;
            cp16(sbase + TBA + r * ROWB + ch * 16,
                 B + (size_t)(colBase + r) * ldB + k0 + ch * 8);
        }
    };

    const uint32_t aOff = (uint32_t)((warp_m * 64 + (lane & 15)) * ROWB + (lane >> 4) * 16);
    const uint32_t bOff = (uint32_t)(TBA +
        (warp_n * 32 + (lane & 7) + ((lane >> 4) & 1) * 8) * ROWB + ((lane >> 3) & 1) * 16);

    loadTile(0, 0); cp_commit();
    loadTile(1, 1); cp_commit();

    for (int it = 0; it < NC; it++) {
        asm volatile("cp.async.wait_group 1;" ::: "memory");
        __syncthreads();
        if (it + 2 < NC) loadTile(it + 2, (it + 2) % NSTG);
        cp_commit();

        const uint32_t sbase = sm + (it % NSTG) * STGB;
#pragma unroll
        for (int ks = 0; ks < 2; ks++) {
            uint32_t a[4][4];
#pragma unroll
            for (int mt = 0; mt < 4; mt++)
                ldm_x4(a[mt][0], a[mt][1], a[mt][2], a[mt][3],
                       sbase + aOff + mt * (16 * ROWB) + ks * 32);
            uint32_t bf[4][2];
#pragma unroll
            for (int np = 0; np < 2; np++) {
                uint32_t r0, r1, r2, r3;
                ldm_x4(r0, r1, r2, r3, sbase + bOff + np * (16 * ROWB) + ks * 32);
                bf[np * 2][0] = r0; bf[np * 2][1] = r1;
                bf[np * 2 + 1][0] = r2; bf[np * 2 + 1][1] = r3;
            }
#pragma unroll
            for (int mt = 0; mt < 4; mt++)
#pragma unroll
                for (int nt = 0; nt < 4; nt++)
                    mma_f16(acc[mt][nt], a[mt], bf[nt]);
        }
    }

    const int gid = lane >> 2, tig = lane & 3;
#pragma unroll
    for (int mt = 0; mt < 4; mt++) {
#pragma unroll
        for (int nt = 0; nt < 4; nt++) {
            int c = colBase + warp_n * 32 + nt * 8 + tig * 2;
            float bv0 = 0.f, bv1 = 0.f;
            if (bias) { bv0 = bias[c]; bv1 = bias[c + 1]; }
#pragma unroll
            for (int half = 0; half < 2; half++) {
                int r = rowBase + warp_m * 64 + mt * 16 + gid + half * 8;
                float v0 = epi_act(acc[mt][nt][half * 2 + 0] + bv0, act);
                float v1 = epi_act(acc[mt][nt][half * 2 + 1] + bv1, act);
                size_t ix = (size_t)r * N + c;
                if (mul) {
                    float2 mm = *(const float2*)(mul + ix);
                    v0 *= mm.x; v1 *= mm.y;
                }
                if (C) {
                    float a0 = v0, a1 = v1;
                    if (addC) {
                        float2 o = *(const float2*)(C + ix);
                        a0 += o.x; a1 += o.y;
                    }
                    float2 w; w.x = a0; w.y = a1;
                    *(float2*)(C + ix) = w;
                }
                if (Csplit) {
                    *reinterpret_cast<__half2*>(Csplit + ix) = __floats2half2_rn(v0, v1);
                }
            }
        }
    }
}

// ===== misc kernels =====
__global__ void embed_kernel(const int* __restrict__ x, const float* __restrict__ emb) {
    int row = blockIdx.x;
    int tok = x[row];
    size_t src = (size_t)tok * Dd, dst = (size_t)row * Dd;
#pragma unroll
    for (int i = 0; i < 4; i++) {
        int c = threadIdx.x + i * 256;
        g_h[dst + c] = emb[src + c];
    }
}

__global__ void __launch_bounds__(256) layernorm_kernel(
    const float* __restrict__ in, const float* __restrict__ in2,
    const float* __restrict__ g, const float* __restrict__ bb,
    float* __restrict__ out, __half* __restrict__ outh)
{
    int row = blockIdx.x;
    size_t base = (size_t)row * Dd;
    float vals[4];
    float s = 0.f, s2 = 0.f;
#pragma unroll
    for (int i = 0; i < 4; i++) {
        int c = threadIdx.x + i * 256;
        float v = in[base + c];
        if (in2) v += in2[base + c];
        vals[i] = v; s += v; s2 += v * v;
    }
    __shared__ float sh1[8], sh2[8];
    s = warpsum(s); s2 = warpsum(s2);
    int w = threadIdx.x >> 5, l = threadIdx.x & 31;
    if (l == 0) { sh1[w] = s; sh2[w] = s2; }
    __syncthreads();
    if (w == 0) {
        float a = (l < 8) ? sh1[l] : 0.f;
        float b2 = (l < 8) ? sh2[l] : 0.f;
        a = warpsum(a); b2 = warpsum(b2);
        if (l == 0) { sh1[0] = a; sh2[0] = b2; }
    }
    __syncthreads();
    float mean = sh1[0] * (1.f / Dd);
    float inv = rsqrtf(sh2[0] * (1.f / Dd) - mean * mean + 1e-5f);
#pragma unroll
    for (int i = 0; i < 4; i++) {
        int c = threadIdx.x + i * 256;
        float v = (vals[i] - mean) * inv * g[c] + bb[c];
        if (out) out[base + c] = v;
        if (outh) outh[base + c] = __float2half_rn(v);
    }
}

// warp-parallel complex scan; writes fp16 ycat directly.
__global__ void __launch_bounds__(256) scan2_kernel(const float* __restrict__ freq) {
    int gwarp = (blockIdx.x * blockDim.x + threadIdx.x) >> 5;
    int lane = threadIdx.x & 31;
    if (gwarp >= Bb * Ff) return;
    int b = gwarp >> 8, f = gwarp & 255;
    float w = 0.1f * freq[f];
    float cw = cosf(w), sw = sinf(w);
    const int L = Tt / 32;
    size_t rbase = (size_t)b * Tt + (size_t)lane * L;

    float Ar = 1.f, Ai = 0.f, Ur = 0.f, Ui = 0.f;
    for (int s = 0; s < L; s++) {
        size_t row = rbase + s;
        float dcy = g_decay[row * Ff + f];
        float ur = g_sp[row * (2 * Ff) + f];
        float ui = g_sp[row * (2 * Ff) + Ff + f];
        float ar = dcy * cw, ai = dcy * sw;
        float nAr = ar * Ar - ai * Ai, nAi = ar * Ai + ai * Ar;
        float nUr = ar * Ur - ai * Ui + ur, nUi = ar * Ui + ai * Ur + ui;
        Ar = nAr; Ai = nAi; Ur = nUr; Ui = nUi;
    }
#pragma unroll
    for (int off = 1; off < 32; off <<= 1) {
        float pAr = __shfl_up_sync(0xffffffffu, Ar, off);
        float pAi = __shfl_up_sync(0xffffffffu, Ai, off);
        float pUr = __shfl_up_sync(0xffffffffu, Ur, off);
        float pUi = __shfl_up_sync(0xffffffffu, Ui, off);
        if (lane >= off) {
            float nAr = Ar * pAr - Ai * pAi;
            float nAi = Ar * pAi + Ai * pAr;
            float nUr = Ar * pUr - Ai * pUi + Ur;
            float nUi = Ar * pUi + Ai * pUr + Ui;
            Ar = nAr; Ai = nAi; Ur = nUr; Ui = nUi;
        }
    }
    float Pr = __shfl_up_sync(0xffffffffu, Ur, 1);
    float Pi = __shfl_up_sync(0xffffffffu, Ui, 1);
    if (lane == 0) { Pr = 0.f; Pi = 0.f; }

    float yr = Pr, yi = Pi;
    for (int s = 0; s < L; s++) {
        size_t row = rbase + s;
        float dcy = g_decay[row * Ff + f];
        float ur = g_sp[row * (2 * Ff) + f];
        float ui = g_sp[row * (2 * Ff) + Ff + f];
        float ar = dcy * cw, ai = dcy * sw;
        float nyr = ar * yr - ai * yi + ur;
        float nyi = ar * yi + ai * yr + ui;
        yr = nyr; yi = nyi;
        a_yc[row * (2 * Ff) + f] = __float2half_rn(yr);
        a_yc[row * (2 * Ff) + Ff + f] = __float2half_rn(yi);
    }
}

__global__ void kl_zero_kernel() { g_accum = 0.f; }
__global__ void __launch_bounds__(256) kl_reduce_kernel() {
    int i = blockIdx.x * blockDim.x + threadIdx.x;
    float v = 0.f;
    if (i < Mrows * LATl) {
        int row = i / LATl, l = i % LATl;
        float mu = g_params[(size_t)row * (2 * LATl) + l];
        float lv = g_params[(size_t)row * (2 * LATl) + LATl + l];
        v = -0.5f * (1.f + lv - mu * mu - expf(lv));
    }
    v = warpsum(v);
    __shared__ float sh[8];
    int w = threadIdx.x >> 5, l = threadIdx.x & 31;
    if (l == 0) sh[w] = v;
    __syncthreads();
    if (w == 0) {
        float a = (l < 8) ? sh[l] : 0.f;
        a = warpsum(a);
        if (l == 0) atomicAdd(&g_accum, a);
    }
}
__global__ void kl_final_kernel(float* __restrict__ out, int do_write) {
    if (do_write) out[0] = 0.01f * fmaxf(g_accum * (1.f / (float)(Mrows * LATl)), 0.05f);
}

// ===== host =====
#define SMEM128 (NSTG * (128 * ROWB + 128 * ROWB))   // 61440
#define SMEM64  (NSTG * (64 * ROWB + 128 * ROWB))    // 46080

static void wsplit_f16(const float* in, __half* out, long rows, int K) {
    long n = rows * K;
    split2_f16_kernel<<<(unsigned)((n + 255) / 256), 256>>>(in, out, n, K);
}
// fp16 2-term: A plain [rows x Ka], B [hi|lo] (2Ka); K' = 2Ka
static void gemm_f16(const __half* A, const __half* B, const float* bias, float* C,
                     const float* mul, __half* Csplit, int N, int Ka, int act, int addC) {
    if (N > 1024) {
        dim3 grid(Mrows / 128, N / 128);
        gemm_mma<128><<<grid, 256, SMEM128>>>(A, B, bias, C, mul, Csplit,
            N, 2 * Ka, Ka, 2 * Ka, Ka, Ka, act, addC);
    } else {
        dim3 grid(Mrows / 64, N / 128);
        gemm_mma<64><<<grid, 128, SMEM64>>>(A, B, bias, C, mul, Csplit,
            N, 2 * Ka, Ka, 2 * Ka, Ka, Ka, act, addC);
    }
}

extern "C" void kernel_launch(void* const* d_in, const int* in_sizes, int n_in,
                              void* d_out, int out_size) {
    (void)in_sizes; (void)n_in;
    const int*   x         = (const int*)  d_in[0];
    const float* emb       = (const float*)d_in[1];
    const float* freq      = (const float*)d_in[2];
    const float* decay_W   = (const float*)d_in[3];
    const float* decay_b   = (const float*)d_in[4];
    const float* spec_in_W = (const float*)d_in[5];
    const float* spec_out_W= (const float*)d_in[6];
    const float* norm1_g   = (const float*)d_in[7];
    const float* norm1_b   = (const float*)d_in[8];
    const float* gate_W    = (const float*)d_in[9];
    const float* gate_b    = (const float*)d_in[10];
    const float* ogate_W   = (const float*)d_in[11];
    const float* ogate_b   = (const float*)d_in[12];
    const float* ffn_g     = (const float*)d_in[13];
    const float* ffn_b     = (const float*)d_in[14];
    const float* ffn_W1    = (const float*)d_in[15];
    const float* ffn_b1    = (const float*)d_in[16];
    const float* ffn_W2    = (const float*)d_in[17];
    const float* ffn_b2    = (const float*)d_in[18];
    const float* vib_g     = (const float*)d_in[19];
    const float* vib_b     = (const float*)d_in[20];
    const float* enc_W     = (const float*)d_in[21];
    const float* enc_b     = (const float*)d_in[22];
    const float* dec_W     = (const float*)d_in[23];
    const float* dec_b     = (const float*)d_in[24];
    const float* normf_g   = (const float*)d_in[25];
    const float* normf_b   = (const float*)d_in[26];
    float* logits = (float*)d_out;

    cudaFuncSetAttribute((const void*)gemm_mma<128>,
                         cudaFuncAttributeMaxDynamicSharedMemorySize, SMEM128);
    cudaFuncSetAttribute((const void*)gemm_mma<64>,
                         cudaFuncAttributeMaxDynamicSharedMemorySize, SMEM64);

    float *p_h, *p_xn, *p_buf1, *p_concept, *p_sp, *p_decay, *p_params;
    cudaGetSymbolAddress((void**)&p_h, g_h);
    cudaGetSymbolAddress((void**)&p_xn, g_xn);
    cudaGetSymbolAddress((void**)&p_buf1, g_buf1);
    cudaGetSymbolAddress((void**)&p_concept, g_concept);
    cudaGetSymbolAddress((void**)&p_sp, g_sp);
    cudaGetSymbolAddress((void**)&p_decay, g_decay);
    cudaGetSymbolAddress((void**)&p_params, g_params);

    __half *pw_gate, *pw_ogate, *pw_decay, *pw_si, *pw_so, *pw_f1, *pw_f2, *pw_enc, *pw_dec, *pw_emb;
    __half *pa_xnh, *pa_uh, *pa_fh, *pa_muh, *pa_yc;
    cudaGetSymbolAddress((void**)&pw_gate, w_gate2);
    cudaGetSymbolAddress((void**)&pw_ogate, w_ogate2);
    cudaGetSymbolAddress((void**)&pw_decay, w_decay2);
    cudaGetSymbolAddress((void**)&pw_si, w_si2);
    cudaGetSymbolAddress((void**)&pw_so, w_so2);
    cudaGetSymbolAddress((void**)&pw_f1, w_f12);
    cudaGetSymbolAddress((void**)&pw_f2, w_f22);
    cudaGetSymbolAddress((void**)&pw_enc, w_enc2);
    cudaGetSymbolAddress((void**)&pw_dec, w_dec2);
    cudaGetSymbolAddress((void**)&pw_emb, w_emb2);
    cudaGetSymbolAddress((void**)&pa_xnh, a_xnh);
    cudaGetSymbolAddress((void**)&pa_uh, a_uh);
    cudaGetSymbolAddress((void**)&pa_fh, a_fh);
    cudaGetSymbolAddress((void**)&pa_muh, a_muh);
    cudaGetSymbolAddress((void**)&pa_yc, a_yc);

    // launches 0-2 feed layer-0 gate GEMM (launch 5 = ncu -s 5 target)
    wsplit_f16(emb, pw_emb, Vv, Dd);                        // 0
    wsplit_f16(gate_W, pw_gate, (long)NLl * Dd, Dd);        // 1
    wsplit_f16(ogate_W, pw_ogate, (long)NLl * Dd, Dd);      // 2
    embed_kernel<<<Mrows, 256>>>(x, emb);                   // 3
    layernorm_kernel<<<Mrows, 256>>>(p_h, nullptr, norm1_g, norm1_b, p_xn, pa_xnh); // 4
    gemm_f16(pa_xnh, pw_gate, gate_b, nullptr, p_xn, pa_uh, Dd, Dd, 1, 0);          // 5

    wsplit_f16(decay_W, pw_decay, (long)NLl * Ff, Dd);
    wsplit_f16(spec_in_W, pw_si, (long)NLl * 2 * Ff, Dd);
    wsplit_f16(spec_out_W, pw_so, (long)NLl * Dd, 2 * Ff);
    wsplit_f16(ffn_W1, pw_f1, (long)NLl * 4 * Dd, Dd);
    wsplit_f16(ffn_W2, pw_f2, (long)NLl * Dd, 4 * Dd);
    wsplit_f16(enc_W, pw_enc, 2 * LATl, Dd);
    wsplit_f16(dec_W, pw_dec, Dd, LATl);

    for (int i = 0; i < NLl; i++) {
        const __half* gW = pw_gate + (size_t)i * Dd * 2 * Dd;
        const __half* oW = pw_ogate + (size_t)i * Dd * 2 * Dd;
        const __half* dW = pw_decay + (size_t)i * Ff * 2 * Dd;
        const __half* siW = pw_si + (size_t)i * 2 * Ff * 2 * Dd;
        const __half* soW = pw_so + (size_t)i * Dd * 2 * 2 * Ff;
        const __half* w1 = pw_f1 + (size_t)i * 4 * Dd * 2 * Dd;
        const __half* w2 = pw_f2 + (size_t)i * Dd * 2 * 4 * Dd;

        if (i > 0) {
            layernorm_kernel<<<Mrows, 256>>>(p_h, nullptr, norm1_g + i * Dd, norm1_b + i * Dd, p_xn, pa_xnh);
            gemm_f16(pa_xnh, gW, gate_b + i * Dd, nullptr, p_xn, pa_uh, Dd, Dd, 1, 0);
        }
        gemm_f16(pa_uh, dW, decay_b + i * Ff, p_decay, nullptr, nullptr, Ff, Dd, 1, 0);
        gemm_f16(pa_uh, siW, nullptr, p_sp, nullptr, nullptr, 2 * Ff, Dd, 0, 0);
        scan2_kernel<<<Bb * Ff * 32 / 256, 256>>>(freq + i * Ff);
        gemm_f16(pa_xnh, oW, ogate_b + i * Dd, p_buf1, nullptr, nullptr, Dd, Dd, 1, 0);
        gemm_f16(pa_yc, soW, nullptr, p_h, p_buf1, nullptr, Dd, 2 * Ff, 0, 1);
        layernorm_kernel<<<Mrows, 256>>>(p_h, nullptr, ffn_g + i * Dd, ffn_b + i * Dd, p_xn, pa_xnh);
        gemm_f16(pa_xnh, w1, ffn_b1 + i * 4 * Dd, nullptr, nullptr, pa_fh, 4 * Dd, Dd, 2, 0);
        gemm_f16(pa_fh, w2, ffn_b2 + i * Dd, p_h, nullptr, nullptr, Dd, 4 * Dd, 0, 1);
    }

    // VIB head
    layernorm_kernel<<<Mrows, 256>>>(p_h, nullptr, vib_g, vib_b, p_xn, pa_xnh);
    gemm_f16(pa_xnh, pw_enc, enc_b, p_params, nullptr, nullptr, 2 * LATl, Dd, 0, 0);
    cvt_mu_kernel<<<(Mrows * LATl + 255) / 256, 256>>>();
    gemm_f16(pa_muh, pw_dec, dec_b, p_concept, nullptr, nullptr, Dd, LATl, 2, 0);
    layernorm_kernel<<<Mrows, 256>>>(p_h, p_concept, normf_g, normf_b, nullptr, pa_xnh);
    gemm_f16(pa_xnh, pw_emb, nullptr, logits, nullptr, nullptr, Vv, Dd, 0, 0);

    kl_zero_kernel<<<1, 1>>>();
    kl_reduce_kernel<<<(Mrows * LATl + 255) / 256, 256>>>();
    int do_write = (out_size >= Mrows * Vv + 1) ? 1 : 0;
    kl_final_kernel<<<1, 1>>>(logits + (size_t)Mrows * Vv, do_write);
}

// round 16
// speedup vs baseline: 1.1119x; 1.0629x over previous
#include <cuda_runtime.h>
#include <cuda_bf16.h>
#include <cuda_fp16.h>
#include <math.h>
#include <stdint.h>

#define Bb   2
#define Tt   2048
#define Vv   32000
#define Dd   1024
#define Ff   256
#define NLl  6
#define LATl 64
#define Mrows (Bb*Tt)

// ===== fp32 scratch =====
__device__ __align__(128) float g_h[Mrows*Dd];
__device__ __align__(128) float g_xn[Mrows*Dd];
__device__ __align__(128) float g_buf1[Mrows*Dd];      // ogate
__device__ __align__(128) float g_concept[Mrows*Dd];
__device__ __align__(128) float g_sp[Mrows*2*Ff];
__device__ __align__(128) float g_decay[Mrows*Ff];
__device__ __align__(128) float g_params[Mrows*2*LATl];
__device__ float g_accum;

// ===== fp16 weights, [hi | lo] along K (row length 2K) =====
// fused gate|ogate: per layer 2048 rows x 2048
__device__ __align__(1024) __half w_go2[(size_t)NLl*2*Dd*2*Dd];
// fused decay|specin: per layer 768 rows x 2048
__device__ __align__(1024) __half w_dsi2[(size_t)NLl*(Ff+2*Ff)*2*Dd];
__device__ __align__(1024) __half w_so2[(size_t)NLl*Dd*2*2*Ff];
__device__ __align__(1024) __half w_f12[(size_t)NLl*4*Dd*2*Dd];
__device__ __align__(1024) __half w_f22[(size_t)NLl*Dd*2*4*Dd];
__device__ __align__(1024) __half w_enc2[2*LATl*2*Dd];
__device__ __align__(1024) __half w_dec2[Dd*2*LATl];
__device__ __align__(1024) __half w_emb2[(size_t)Vv*2*Dd];
// fp16 activations (plain hi)
__device__ __align__(1024) __half a_xnh[(size_t)Mrows*Dd];
__device__ __align__(1024) __half a_uh[(size_t)Mrows*Dd];
__device__ __align__(1024) __half a_fh[(size_t)Mrows*4*Dd];
__device__ __align__(1024) __half a_yc[(size_t)Mrows*2*Ff];
__device__ __align__(1024) __half a_muh[(size_t)Mrows*LATl];

// ===== helpers =====
__inline__ __device__ float warpsum(float v) {
#pragma unroll
    for (int o = 16; o > 0; o >>= 1) v += __shfl_xor_sync(0xffffffffu, v, o);
    return v;
}
__device__ __forceinline__ uint32_t smem_u32(const void* p) {
    uint32_t a;
    asm("{ .reg .u64 t; cvta.to.shared.u64 t, %1; cvt.u32.u64 %0, t; }" : "=r"(a) : "l"(p));
    return a;
}
__device__ __forceinline__ void cp16(uint32_t dst, const void* src) {
    asm volatile("cp.async.cg.shared.global [%0], [%1], 16;" :: "r"(dst), "l"(src));
}
__device__ __forceinline__ void cp_commit() { asm volatile("cp.async.commit_group;" ::: "memory"); }
__device__ __forceinline__ void ldm_x4(uint32_t& r0, uint32_t& r1, uint32_t& r2, uint32_t& r3, uint32_t addr) {
    asm volatile("ldmatrix.sync.aligned.m8n8.x4.shared.b16 {%0,%1,%2,%3}, [%4];"
                 : "=r"(r0), "=r"(r1), "=r"(r2), "=r"(r3) : "r"(addr));
}
__device__ __forceinline__ void mma_f16(float* c, const uint32_t* a, const uint32_t* b) {
    asm volatile("mma.sync.aligned.m16n8k16.row.col.f32.f16.f16.f32 "
                 "{%0,%1,%2,%3}, {%4,%5,%6,%7}, {%8,%9}, {%0,%1,%2,%3};"
                 : "+f"(c[0]), "+f"(c[1]), "+f"(c[2]), "+f"(c[3])
                 : "r"(a[0]), "r"(a[1]), "r"(a[2]), "r"(a[3]), "r"(b[0]), "r"(b[1]));
}
__device__ __forceinline__ float epi_act(float v, int act) {
    if (act == 1) return 1.0f / (1.0f + expf(-v));
    if (act == 2) return 0.5f * v * (1.0f + erff(v * 0.70710678118654752f));
    return v;
}

// ===== weight split =====
__global__ void split2_f16_kernel(const float* __restrict__ in, __half* __restrict__ out,
                                  long n, int K) {
    long i = (long)blockIdx.x * blockDim.x + threadIdx.x;
    if (i >= n) return;
    long m = i / K; int k = (int)(i - m * K);
    float x = in[i];
    __half hi = __float2half_rn(x);
    __half lo = __float2half_rn(x - __half2float(hi));
    long ob = m * (long)(2 * K);
    out[ob + k] = hi; out[ob + K + k] = lo;
}
__global__ void cvt_mu_kernel() {
    int i = blockIdx.x * blockDim.x + threadIdx.x;
    if (i >= Mrows * LATl) return;
    int m = i >> 6, l = i & 63;
    a_muh[i] = __float2half_rn(g_params[(size_t)m * (2 * LATl) + l]);
}

#define ROWB 80
#define NSTG 3

// ===== HMMA GEMM with column-split dual epilogue =====
// acc[m,n] = sum_{k<K} A[m,mapA(k)] * B[n,k]   (A fp16 plain, B fp16 [hi|lo])
// cols < splitN : v=act1(acc+bias1[c]);       (opt) v*=mul[r*splitN+c];
//                 C1 (fp32, stride splitN, opt +=) and/or C1h (fp16)
// cols >= splitN: v=act2(acc+bias2[c-splitN]); C2 (fp32, stride N-splitN)
template<int BM>
__global__ void __launch_bounds__(BM == 128 ? 256 : 128, BM == 128 ? 2 : 4) gemm_mma(
    const __half* __restrict__ A, const __half* __restrict__ B,
    const float* __restrict__ bias1, const float* __restrict__ bias2,
    int N, int splitN, int K, int ldA, int ldB, int limA, int subA,
    int act1, int act2, const float* __restrict__ mul,
    float* __restrict__ C1, __half* __restrict__ C1h, int addC1,
    float* __restrict__ C2)
{
    constexpr int NTHR = (BM == 128) ? 256 : 128;
    constexpr int TBA = BM * ROWB;
    constexpr int TBB = 128 * ROWB;
    constexpr int STGB = TBA + TBB;

    extern __shared__ char dsm[];
    const uint32_t sm = smem_u32(dsm);
    const int tid = threadIdx.x;
    const int wid = tid >> 5, lane = tid & 31;
    const int warp_m = (BM == 128) ? (wid >> 2) : 0;
    const int warp_n = wid & 3;
    const int rowBase = blockIdx.x * BM;
    const int colBase = blockIdx.y * 128;
    const int NC = K >> 5;

    float acc[4][4][4];
#pragma unroll
    for (int i = 0; i < 4; i++)
#pragma unroll
        for (int j = 0; j < 4; j++)
#pragma unroll
            for (int q = 0; q < 4; q++) acc[i][j][q] = 0.f;

    auto loadTile = [&](int it, int stg) {
        const int k0 = it * 32;
        const int kA = k0 >= limA ? k0 - subA : k0;
        const uint32_t sbase = sm + stg * STGB;
#pragma unroll
        for (int i = 0; i < BM * 4 / NTHR; i++) {
            int c = tid + i * NTHR;
            int r = c >> 2, ch = c & 3;
            cp16(sbase + r * ROWB + ch * 16,
                 A + (size_t)(rowBase + r) * ldA + kA + ch * 8);
        }
#pragma unroll
        for (int i = 0; i < 512 / NTHR; i++) {
            int c = tid + i * NTHR;
            int r = c >> 2, ch = c & 3;
            cp16(sbase + TBA + r * ROWB + ch * 16,
                 B + (size_t)(colBase + r) * ldB + k0 + ch * 8);
        }
    };

    const uint32_t aOff = (uint32_t)((warp_m * 64 + (lane & 15)) * ROWB + (lane >> 4) * 16);
    const uint32_t bOff = (uint32_t)(TBA +
        (warp_n * 32 + (lane & 7) + ((lane >> 4) & 1) * 8) * ROWB + ((lane >> 3) & 1) * 16);

    loadTile(0, 0); cp_commit();
    loadTile(1, 1); cp_commit();

    for (int it = 0; it < NC; it++) {
        asm volatile("cp.async.wait_group 1;" ::: "memory");
        __syncthreads();
        if (it + 2 < NC) loadTile(it + 2, (it + 2) % NSTG);
        cp_commit();

        const uint32_t sbase = sm + (it % NSTG) * STGB;
#pragma unroll
        for (int ks = 0; ks < 2; ks++) {
            uint32_t a[4][4];
#pragma unroll
            for (int mt = 0; mt < 4; mt++)
                ldm_x4(a[mt][0], a[mt][1], a[mt][2], a[mt][3],
                       sbase + aOff + mt * (16 * ROWB) + ks * 32);
            uint32_t bf[4][2];
#pragma unroll
            for (int np = 0; np < 2; np++) {
                uint32_t r0, r1, r2, r3;
                ldm_x4(r0, r1, r2, r3, sbase + bOff + np * (16 * ROWB) + ks * 32);
                bf[np * 2][0] = r0; bf[np * 2][1] = r1;
                bf[np * 2 + 1][0] = r2; bf[np * 2 + 1][1] = r3;
            }
#pragma unroll
            for (int mt = 0; mt < 4; mt++)
#pragma unroll
                for (int nt = 0; nt < 4; nt++)
                    mma_f16(acc[mt][nt], a[mt], bf[nt]);
        }
    }

    const int gid = lane >> 2, tig = lane & 3;
#pragma unroll
    for (int mt = 0; mt < 4; mt++) {
#pragma unroll
        for (int nt = 0; nt < 4; nt++) {
            int c = colBase + warp_n * 32 + nt * 8 + tig * 2;
            bool firstHalf = (c < splitN);
            float bv0, bv1;
            if (firstHalf) {
                bv0 = bias1 ? bias1[c] : 0.f;
                bv1 = bias1 ? bias1[c + 1] : 0.f;
            } else {
                bv0 = bias2 ? bias2[c - splitN] : 0.f;
                bv1 = bias2 ? bias2[c + 1 - splitN] : 0.f;
            }
            int act = firstHalf ? act1 : act2;
#pragma unroll
            for (int half = 0; half < 2; half++) {
                int r = rowBase + warp_m * 64 + mt * 16 + gid + half * 8;
                float v0 = epi_act(acc[mt][nt][half * 2 + 0] + bv0, act);
                float v1 = epi_act(acc[mt][nt][half * 2 + 1] + bv1, act);
                if (firstHalf) {
                    size_t ix = (size_t)r * splitN + c;
                    if (mul) {
                        float2 mm = *(const float2*)(mul + ix);
                        v0 *= mm.x; v1 *= mm.y;
                    }
                    if (C1) {
                        float a0 = v0, a1 = v1;
                        if (addC1) {
                            float2 o = *(const float2*)(C1 + ix);
                            a0 += o.x; a1 += o.y;
                        }
                        float2 w; w.x = a0; w.y = a1;
                        *(float2*)(C1 + ix) = w;
                    }
                    if (C1h) {
                        *reinterpret_cast<__half2*>(C1h + ix) = __floats2half2_rn(v0, v1);
                    }
                } else {
                    size_t ix = (size_t)r * (N - splitN) + (c - splitN);
                    float2 w; w.x = v0; w.y = v1;
                    *(float2*)(C2 + ix) = w;
                }
            }
        }
    }
}

// ===== misc kernels =====
__global__ void embed_kernel(const int* __restrict__ x, const float* __restrict__ emb) {
    int row = blockIdx.x;
    int tok = x[row];
    size_t src = (size_t)tok * Dd, dst = (size_t)row * Dd;
#pragma unroll
    for (int i = 0; i < 4; i++) {
        int c = threadIdx.x + i * 256;
        g_h[dst + c] = emb[src + c];
    }
}

__global__ void __launch_bounds__(256) layernorm_kernel(
    const float* __restrict__ in, const float* __restrict__ in2,
    const float* __restrict__ g, const float* __restrict__ bb,
    float* __restrict__ out, __half* __restrict__ outh)
{
    int row = blockIdx.x;
    size_t base = (size_t)row * Dd;
    float vals[4];
    float s = 0.f, s2 = 0.f;
#pragma unroll
    for (int i = 0; i < 4; i++) {
        int c = threadIdx.x + i * 256;
        float v = in[base + c];
        if (in2) v += in2[base + c];
        vals[i] = v; s += v; s2 += v * v;
    }
    __shared__ float sh1[8], sh2[8];
    s = warpsum(s); s2 = warpsum(s2);
    int w = threadIdx.x >> 5, l = threadIdx.x & 31;
    if (l == 0) { sh1[w] = s; sh2[w] = s2; }
    __syncthreads();
    if (w == 0) {
        float a = (l < 8) ? sh1[l] : 0.f;
        float b2 = (l < 8) ? sh2[l] : 0.f;
        a = warpsum(a); b2 = warpsum(b2);
        if (l == 0) { sh1[0] = a; sh2[0] = b2; }
    }
    __syncthreads();
    float mean = sh1[0] * (1.f / Dd);
    float inv = rsqrtf(sh2[0] * (1.f / Dd) - mean * mean + 1e-5f);
#pragma unroll
    for (int i = 0; i < 4; i++) {
        int c = threadIdx.x + i * 256;
        float v = (vals[i] - mean) * inv * g[c] + bb[c];
        if (out) out[base + c] = v;
        if (outh) outh[base + c] = __float2half_rn(v);
    }
}

// warp-parallel complex scan; writes fp16 ycat directly.
__global__ void __launch_bounds__(256) scan2_kernel(const float* __restrict__ freq) {
    int gwarp = (blockIdx.x * blockDim.x + threadIdx.x) >> 5;
    int lane = threadIdx.x & 31;
    if (gwarp >= Bb * Ff) return;
    int b = gwarp >> 8, f = gwarp & 255;
    float w = 0.1f * freq[f];
    float cw = cosf(w), sw = sinf(w);
    const int L = Tt / 32;
    size_t rbase = (size_t)b * Tt + (size_t)lane * L;

    float Ar = 1.f, Ai = 0.f, Ur = 0.f, Ui = 0.f;
    for (int s = 0; s < L; s++) {
        size_t row = rbase + s;
        float dcy = g_decay[row * Ff + f];
        float ur = g_sp[row * (2 * Ff) + f];
        float ui = g_sp[row * (2 * Ff) + Ff + f];
        float ar = dcy * cw, ai = dcy * sw;
        float nAr = ar * Ar - ai * Ai, nAi = ar * Ai + ai * Ar;
        float nUr = ar * Ur - ai * Ui + ur, nUi = ar * Ui + ai * Ur + ui;
        Ar = nAr; Ai = nAi; Ur = nUr; Ui = nUi;
    }
#pragma unroll
    for (int off = 1; off < 32; off <<= 1) {
        float pAr = __shfl_up_sync(0xffffffffu, Ar, off);
        float pAi = __shfl_up_sync(0xffffffffu, Ai, off);
        float pUr = __shfl_up_sync(0xffffffffu, Ur, off);
        float pUi = __shfl_up_sync(0xffffffffu, Ui, off);
        if (lane >= off) {
            float nAr = Ar * pAr - Ai * pAi;
            float nAi = Ar * pAi + Ai * pAr;
            float nUr = Ar * pUr - Ai * pUi + Ur;
            float nUi = Ar * pUi + Ai * pUr + Ui;
            Ar = nAr; Ai = nAi; Ur = nUr; Ui = nUi;
        }
    }
    float Pr = __shfl_up_sync(0xffffffffu, Ur, 1);
    float Pi = __shfl_up_sync(0xffffffffu, Ui, 1);
    if (lane == 0) { Pr = 0.f; Pi = 0.f; }

    float yr = Pr, yi = Pi;
    for (int s = 0; s < L; s++) {
        size_t row = rbase + s;
        float dcy = g_decay[row * Ff + f];
        float ur = g_sp[row * (2 * Ff) + f];
        float ui = g_sp[row * (2 * Ff) + Ff + f];
        float ar = dcy * cw, ai = dcy * sw;
        float nyr = ar * yr - ai * yi + ur;
        float nyi = ar * yi + ai * yr + ui;
        yr = nyr; yi = nyi;
        a_yc[row * (2 * Ff) + f] = __float2half_rn(yr);
        a_yc[row * (2 * Ff) + Ff + f] = __float2half_rn(yi);
    }
}

__global__ void kl_zero_kernel() { g_accum = 0.f; }
__global__ void __launch_bounds__(256) kl_reduce_kernel() {
    int i = blockIdx.x * blockDim.x + threadIdx.x;
    float v = 0.f;
    if (i < Mrows * LATl) {
        int row = i / LATl, l = i % LATl;
        float mu = g_params[(size_t)row * (2 * LATl) + l];
        float lv = g_params[(size_t)row * (2 * LATl) + LATl + l];
        v = -0.5f * (1.f + lv - mu * mu - expf(lv));
    }
    v = warpsum(v);
    __shared__ float sh[8];
    int w = threadIdx.x >> 5, l = threadIdx.x & 31;
    if (l == 0) sh[w] = v;
    __syncthreads();
    if (w == 0) {
        float a = (l < 8) ? sh[l] : 0.f;
        a = warpsum(a);
        if (l == 0) atomicAdd(&g_accum, a);
    }
}
__global__ void kl_final_kernel(float* __restrict__ out, int do_write) {
    if (do_write) out[0] = 0.01f * fmaxf(g_accum * (1.f / (float)(Mrows * LATl)), 0.05f);
}

// ===== host =====
#define SMEM128 (NSTG * (128 * ROWB + 128 * ROWB))   // 61440
#define SMEM64  (NSTG * (64 * ROWB + 128 * ROWB))    // 46080

static void wsplit_f16(const float* in, __half* out, long rows, int K) {
    long n = rows * K;
    split2_f16_kernel<<<(unsigned)((n + 255) / 256), 256>>>(in, out, n, K);
}
// generic call: K' = 2Ka, A plain fp16 stride Ka (k-fold map), B [hi|lo] stride 2Ka
static void gemmx(const __half* A, const __half* B,
                  const float* bias1, const float* bias2,
                  int N, int splitN, int Ka, int act1, int act2,
                  const float* mul, float* C1, __half* C1h, int addC1, float* C2) {
    if (N > 1024) {
        dim3 grid(Mrows / 128, N / 128);
        gemm_mma<128><<<grid, 256, SMEM128>>>(A, B, bias1, bias2,
            N, splitN, 2 * Ka, Ka, 2 * Ka, Ka, Ka, act1, act2, mul, C1, C1h, addC1, C2);
    } else {
        dim3 grid(Mrows / 64, N / 128);
        gemm_mma<64><<<grid, 128, SMEM64>>>(A, B, bias1, bias2,
            N, splitN, 2 * Ka, Ka, 2 * Ka, Ka, Ka, act1, act2, mul, C1, C1h, addC1, C2);
    }
}

extern "C" void kernel_launch(void* const* d_in, const int* in_sizes, int n_in,
                              void* d_out, int out_size) {
    (void)in_sizes; (void)n_in;
    const int*   x         = (const int*)  d_in[0];
    const float* emb       = (const float*)d_in[1];
    const float* freq      = (const float*)d_in[2];
    const float* decay_W   = (const float*)d_in[3];
    const float* decay_b   = (const float*)d_in[4];
    const float* spec_in_W = (const float*)d_in[5];
    const float* spec_out_W= (const float*)d_in[6];
    const float* norm1_g   = (const float*)d_in[7];
    const float* norm1_b   = (const float*)d_in[8];
    const float* gate_W    = (const float*)d_in[9];
    const float* gate_b    = (const float*)d_in[10];
    const float* ogate_W   = (const float*)d_in[11];
    const float* ogate_b   = (const float*)d_in[12];
    const float* ffn_g     = (const float*)d_in[13];
    const float* ffn_b     = (const float*)d_in[14];
    const float* ffn_W1    = (const float*)d_in[15];
    const float* ffn_b1    = (const float*)d_in[16];
    const float* ffn_W2    = (const float*)d_in[17];
    const float* ffn_b2    = (const float*)d_in[18];
    const float* vib_g     = (const float*)d_in[19];
    const float* vib_b     = (const float*)d_in[20];
    const float* enc_W     = (const float*)d_in[21];
    const float* enc_b     = (const float*)d_in[22];
    const float* dec_W     = (const float*)d_in[23];
    const float* dec_b     = (const float*)d_in[24];
    const float* normf_g   = (const float*)d_in[25];
    const float* normf_b   = (const float*)d_in[26];
    float* logits = (float*)d_out;

    cudaFuncSetAttribute((const void*)gemm_mma<128>,
                         cudaFuncAttributeMaxDynamicSharedMemorySize, SMEM128);
    cudaFuncSetAttribute((const void*)gemm_mma<64>,
                         cudaFuncAttributeMaxDynamicSharedMemorySize, SMEM64);

    float *p_h, *p_xn, *p_buf1, *p_concept, *p_sp, *p_decay, *p_params;
    cudaGetSymbolAddress((void**)&p_h, g_h);
    cudaGetSymbolAddress((void**)&p_xn, g_xn);
    cudaGetSymbolAddress((void**)&p_buf1, g_buf1);
    cudaGetSymbolAddress((void**)&p_concept, g_concept);
    cudaGetSymbolAddress((void**)&p_sp, g_sp);
    cudaGetSymbolAddress((void**)&p_decay, g_decay);
    cudaGetSymbolAddress((void**)&p_params, g_params);

    __half *pw_go, *pw_dsi, *pw_so, *pw_f1, *pw_f2, *pw_enc, *pw_dec, *pw_emb;
    __half *pa_xnh, *pa_uh, *pa_fh, *pa_muh, *pa_yc;
    cudaGetSymbolAddress((void**)&pw_go, w_go2);
    cudaGetSymbolAddress((void**)&pw_dsi, w_dsi2);
    cudaGetSymbolAddress((void**)&pw_so, w_so2);
    cudaGetSymbolAddress((void**)&pw_f1, w_f12);
    cudaGetSymbolAddress((void**)&pw_f2, w_f22);
    cudaGetSymbolAddress((void**)&pw_enc, w_enc2);
    cudaGetSymbolAddress((void**)&pw_dec, w_dec2);
    cudaGetSymbolAddress((void**)&pw_emb, w_emb2);
    cudaGetSymbolAddress((void**)&pa_xnh, a_xnh);
    cudaGetSymbolAddress((void**)&pa_uh, a_uh);
    cudaGetSymbolAddress((void**)&pa_fh, a_fh);
    cudaGetSymbolAddress((void**)&pa_muh, a_muh);
    cudaGetSymbolAddress((void**)&pa_yc, a_yc);

    // weight converts: fused gate|ogate and decay|specin row-concat per layer
    wsplit_f16(emb, pw_emb, Vv, Dd);
    for (int i = 0; i < NLl; i++) {
        __half* go = pw_go + (size_t)i * 2 * Dd * 2 * Dd;
        wsplit_f16(gate_W + (size_t)i * Dd * Dd, go, Dd, Dd);
        wsplit_f16(ogate_W + (size_t)i * Dd * Dd, go + (size_t)Dd * 2 * Dd, Dd, Dd);
        __half* dsi = pw_dsi + (size_t)i * 768 * 2 * Dd;
        wsplit_f16(decay_W + (size_t)i * Ff * Dd, dsi, Ff, Dd);
        wsplit_f16(spec_in_W + (size_t)i * 2 * Ff * Dd, dsi + (size_t)Ff * 2 * Dd, 2 * Ff, Dd);
    }
    wsplit_f16(spec_out_W, pw_so, (long)NLl * Dd, 2 * Ff);
    wsplit_f16(ffn_W1, pw_f1, (long)NLl * 4 * Dd, Dd);
    wsplit_f16(ffn_W2, pw_f2, (long)NLl * Dd, 4 * Dd);
    wsplit_f16(enc_W, pw_enc, 2 * LATl, Dd);
    wsplit_f16(dec_W, pw_dec, Dd, LATl);

    embed_kernel<<<Mrows, 256>>>(x, emb);

    for (int i = 0; i < NLl; i++) {
        const __half* goW = pw_go + (size_t)i * 2 * Dd * 2 * Dd;
        const __half* dsiW = pw_dsi + (size_t)i * 768 * 2 * Dd;
        const __half* soW = pw_so + (size_t)i * Dd * 2 * 2 * Ff;
        const __half* w1 = pw_f1 + (size_t)i * 4 * Dd * 2 * Dd;
        const __half* w2 = pw_f2 + (size_t)i * Dd * 2 * 4 * Dd;

        layernorm_kernel<<<Mrows, 256>>>(p_h, nullptr, norm1_g + i * Dd, norm1_b + i * Dd, p_xn, pa_xnh);
        // fused gate|ogate: cols<1024 -> u = xn*sigmoid (fp16); cols>=1024 -> ogate sigmoid (fp32)
        gemmx(pa_xnh, goW, gate_b + i * Dd, ogate_b + i * Dd,
              2 * Dd, Dd, Dd, 1, 1, p_xn, nullptr, pa_uh, 0, p_buf1);
        // fused decay|specin: cols<256 -> sigmoid decay; cols>=256 -> sp
        gemmx(pa_uh, dsiW, decay_b + i * Ff, nullptr,
              768, Ff, Dd, 1, 0, nullptr, p_decay, nullptr, 0, p_sp);
        scan2_kernel<<<Bb * Ff * 32 / 256, 256>>>(freq + i * Ff);
        // h += (ycat @ soW.T) * ogate
        gemmx(pa_yc, soW, nullptr, nullptr,
              Dd, Dd, 2 * Ff, 0, 0, p_buf1, p_h, nullptr, 1, nullptr);
        layernorm_kernel<<<Mrows, 256>>>(p_h, nullptr, ffn_g + i * Dd, ffn_b + i * Dd, nullptr, pa_xnh);
        gemmx(pa_xnh, w1, ffn_b1 + i * 4 * Dd, nullptr,
              4 * Dd, 4 * Dd, Dd, 2, 0, nullptr, nullptr, pa_fh, 0, nullptr);
        gemmx(pa_fh, w2, ffn_b2 + i * Dd, nullptr,
              Dd, Dd, 4 * Dd, 0, 0, nullptr, p_h, nullptr, 1, nullptr);
    }

    // VIB head
    layernorm_kernel<<<Mrows, 256>>>(p_h, nullptr, vib_g, vib_b, nullptr, pa_xnh);
    gemmx(pa_xnh, pw_enc, enc_b, nullptr,
          2 * LATl, 2 * LATl, Dd, 0, 0, nullptr, p_params, nullptr, 0, nullptr);
    cvt_mu_kernel<<<(Mrows * LATl + 255) / 256, 256>>>();
    gemmx(pa_muh, pw_dec, dec_b, nullptr,
          Dd, Dd, LATl, 2, 0, nullptr, p_concept, nullptr, 0, nullptr);
    layernorm_kernel<<<Mrows, 256>>>(p_h, p_concept, normf_g, normf_b, nullptr, pa_xnh);
    gemmx(pa_xnh, pw_emb, nullptr, nullptr,
          Vv, Vv, Dd, 0, 0, nullptr, logits, nullptr, 0, nullptr);

    kl_zero_kernel<<<1, 1>>>();
    kl_reduce_kernel<<<(Mrows * LATl + 255) / 256, 256>>>();
    int do_write = (out_size >= Mrows * Vv + 1) ? 1 : 0;
    kl_final_kernel<<<1, 1>>>(logits + (size_t)Mrows * Vv, do_write);
}

// round 17
// speedup vs baseline: 1.1215x; 1.0087x over previous
#include <cuda_runtime.h>
#include <cuda_bf16.h>
#include <cuda_fp16.h>
#include <math.h>
#include <stdint.h>

#define Bb   2
#define Tt   2048
#define Vv   32000
#define Dd   1024
#define Ff   256
#define NLl  6
#define LATl 64
#define Mrows (Bb*Tt)

// ===== fp32 scratch =====
__device__ __align__(128) float g_h[Mrows*Dd];
__device__ __align__(128) float g_xn[Mrows*Dd];
__device__ __align__(128) float g_buf1[Mrows*Dd];      // ogate
__device__ __align__(128) float g_concept[Mrows*Dd];
__device__ __align__(128) float g_sp[Mrows*2*Ff];
__device__ __align__(128) float g_decay[Mrows*Ff];
__device__ __align__(128) float g_params[Mrows*2*LATl];
__device__ float g_accum;

// ===== fp16 weights, [hi | lo] along K (row length 2K) =====
__device__ __align__(1024) __half w_go2[(size_t)NLl*2*Dd*2*Dd];     // gate|ogate fused
__device__ __align__(1024) __half w_dsi2[(size_t)NLl*(Ff+2*Ff)*2*Dd]; // decay|specin fused
__device__ __align__(1024) __half w_so2[(size_t)NLl*Dd*2*2*Ff];
__device__ __align__(1024) __half w_f12[(size_t)NLl*4*Dd*2*Dd];
__device__ __align__(1024) __half w_f22[(size_t)NLl*Dd*2*4*Dd];
__device__ __align__(1024) __half w_enc2[2*LATl*2*Dd];
__device__ __align__(1024) __half w_dec2[Dd*2*LATl];
__device__ __align__(1024) __half w_emb2[(size_t)Vv*2*Dd];
// fp16 activations (plain hi)
__device__ __align__(1024) __half a_xnh[(size_t)Mrows*Dd];
__device__ __align__(1024) __half a_uh[(size_t)Mrows*Dd];
__device__ __align__(1024) __half a_fh[(size_t)Mrows*4*Dd];
__device__ __align__(1024) __half a_yc[(size_t)Mrows*2*Ff];
__device__ __align__(1024) __half a_muh[(size_t)Mrows*LATl];

// ===== helpers =====
__inline__ __device__ float warpsum(float v) {
#pragma unroll
    for (int o = 16; o > 0; o >>= 1) v += __shfl_xor_sync(0xffffffffu, v, o);
    return v;
}
__device__ __forceinline__ uint32_t smem_u32(const void* p) {
    uint32_t a;
    asm("{ .reg .u64 t; cvta.to.shared.u64 t, %1; cvt.u32.u64 %0, t; }" : "=r"(a) : "l"(p));
    return a;
}
__device__ __forceinline__ void cp16(uint32_t dst, const void* src) {
    asm volatile("cp.async.cg.shared.global [%0], [%1], 16;" :: "r"(dst), "l"(src));
}
__device__ __forceinline__ void cp_commit() { asm volatile("cp.async.commit_group;" ::: "memory"); }
__device__ __forceinline__ void ldm_x4(uint32_t& r0, uint32_t& r1, uint32_t& r2, uint32_t& r3, uint32_t addr) {
    asm volatile("ldmatrix.sync.aligned.m8n8.x4.shared.b16 {%0,%1,%2,%3}, [%4];"
                 : "=r"(r0), "=r"(r1), "=r"(r2), "=r"(r3) : "r"(addr));
}
__device__ __forceinline__ void mma_f16(float* c, const uint32_t* a, const uint32_t* b) {
    asm volatile("mma.sync.aligned.m16n8k16.row.col.f32.f16.f16.f32 "
                 "{%0,%1,%2,%3}, {%4,%5,%6,%7}, {%8,%9}, {%0,%1,%2,%3};"
                 : "+f"(c[0]), "+f"(c[1]), "+f"(c[2]), "+f"(c[3])
                 : "r"(a[0]), "r"(a[1]), "r"(a[2]), "r"(a[3]), "r"(b[0]), "r"(b[1]));
}
__device__ __forceinline__ float epi_act(float v, int act) {
    if (act == 1) return 1.0f / (1.0f + expf(-v));
    if (act == 2) return 0.5f * v * (1.0f + erff(v * 0.70710678118654752f));
    return v;
}

// ===== weight split =====
__global__ void split2_f16_kernel(const float* __restrict__ in, __half* __restrict__ out,
                                  long n, int K) {
    long i = (long)blockIdx.x * blockDim.x + threadIdx.x;
    if (i >= n) return;
    long m = i / K; int k = (int)(i - m * K);
    float x = in[i];
    __half hi = __float2half_rn(x);
    __half lo = __float2half_rn(x - __half2float(hi));
    long ob = m * (long)(2 * K);
    out[ob + k] = hi; out[ob + K + k] = lo;
}
__global__ void cvt_mu_kernel() {
    int i = blockIdx.x * blockDim.x + threadIdx.x;
    if (i >= Mrows * LATl) return;
    int m = i >> 6, l = i & 63;
    a_muh[i] = __float2half_rn(g_params[(size_t)m * (2 * LATl) + l]);
}

#define ROWB 80

// ===== HMMA GEMM with column-split dual epilogue =====
// acc[m,n] = sum_{k<K} A[m,mapA(k)] * B[n,k]   (A fp16 plain, B fp16 [hi|lo])
// cols < splitN : v=act1(acc+bias1[c]); (opt) v*=mul; -> C1 (fp32,+=opt) / C1h (fp16)
// cols >= splitN: v=act2(acc+bias2[c-splitN]); -> C2 (fp32, stride N-splitN)
template<int BM>
__global__ void __launch_bounds__(BM == 128 ? 256 : 128, BM == 128 ? 2 : 4) gemm_mma(
    const __half* __restrict__ A, const __half* __restrict__ B,
    const float* __restrict__ bias1, const float* __restrict__ bias2,
    int N, int splitN, int K, int ldA, int ldB, int limA, int subA,
    int act1, int act2, const float* __restrict__ mul,
    float* __restrict__ C1, __half* __restrict__ C1h, int addC1,
    float* __restrict__ C2)
{
    constexpr int NTHR = (BM == 128) ? 256 : 128;
    constexpr int NSTG = (BM == 128) ? 4 : 3;
    constexpr int TBA = BM * ROWB;
    constexpr int TBB = 128 * ROWB;
    constexpr int STGB = TBA + TBB;

    extern __shared__ char dsm[];
    const uint32_t sm = smem_u32(dsm);
    const int tid = threadIdx.x;
    const int wid = tid >> 5, lane = tid & 31;
    const int warp_m = (BM == 128) ? (wid >> 2) : 0;
    const int warp_n = wid & 3;
    const int rowBase = blockIdx.x * BM;
    const int colBase = blockIdx.y * 128;
    const int NC = K >> 5;

    float acc[4][4][4];
#pragma unroll
    for (int i = 0; i < 4; i++)
#pragma unroll
        for (int j = 0; j < 4; j++)
#pragma unroll
            for (int q = 0; q < 4; q++) acc[i][j][q] = 0.f;

    auto loadTile = [&](int it, int stg) {
        const int k0 = it * 32;
        const int kA = k0 >= limA ? k0 - subA : k0;
        const uint32_t sbase = sm + stg * STGB;
#pragma unroll
        for (int i = 0; i < BM * 4 / NTHR; i++) {
            int c = tid + i * NTHR;
            int r = c >> 2, ch = c & 3;
            cp16(sbase + r * ROWB + ch * 16,
                 A + (size_t)(rowBase + r) * ldA + kA + ch * 8);
        }
#pragma unroll
        for (int i = 0; i < 512 / NTHR; i++) {
            int c = tid + i * NTHR;
            int r = c >> 2, ch = c & 3;
            cp16(sbase + TBA + r * ROWB + ch * 16,
                 B + (size_t)(colBase + r) * ldB + k0 + ch * 8);
        }
    };

    const uint32_t aOff = (uint32_t)((warp_m * 64 + (lane & 15)) * ROWB + (lane >> 4) * 16);
    const uint32_t bOff = (uint32_t)(TBA +
        (warp_n * 32 + (lane & 7) + ((lane >> 4) & 1) * 8) * ROWB + ((lane >> 3) & 1) * 16);

    // prefetch NSTG-1 stages
#pragma unroll
    for (int p = 0; p < NSTG - 1; p++) {
        if (p < NC) loadTile(p, p);
        cp_commit();
    }

    for (int it = 0; it < NC; it++) {
        asm volatile("cp.async.wait_group %0;" :: "n"(NSTG - 2) : "memory");
        __syncthreads();
        if (it + NSTG - 1 < NC) loadTile(it + NSTG - 1, (it + NSTG - 1) % NSTG);
        cp_commit();

        const uint32_t sbase = sm + (it % NSTG) * STGB;
#pragma unroll
        for (int ks = 0; ks < 2; ks++) {
            uint32_t a[4][4];
#pragma unroll
            for (int mt = 0; mt < 4; mt++)
                ldm_x4(a[mt][0], a[mt][1], a[mt][2], a[mt][3],
                       sbase + aOff + mt * (16 * ROWB) + ks * 32);
            uint32_t bf[4][2];
#pragma unroll
            for (int np = 0; np < 2; np++) {
                uint32_t r0, r1, r2, r3;
                ldm_x4(r0, r1, r2, r3, sbase + bOff + np * (16 * ROWB) + ks * 32);
                bf[np * 2][0] = r0; bf[np * 2][1] = r1;
                bf[np * 2 + 1][0] = r2; bf[np * 2 + 1][1] = r3;
            }
#pragma unroll
            for (int mt = 0; mt < 4; mt++)
#pragma unroll
                for (int nt = 0; nt < 4; nt++)
                    mma_f16(acc[mt][nt], a[mt], bf[nt]);
        }
    }

    const int gid = lane >> 2, tig = lane & 3;
#pragma unroll
    for (int mt = 0; mt < 4; mt++) {
#pragma unroll
        for (int nt = 0; nt < 4; nt++) {
            int c = colBase + warp_n * 32 + nt * 8 + tig * 2;
            bool firstHalf = (c < splitN);
            float bv0, bv1;
            if (firstHalf) {
                bv0 = bias1 ? bias1[c] : 0.f;
                bv1 = bias1 ? bias1[c + 1] : 0.f;
            } else {
                bv0 = bias2 ? bias2[c - splitN] : 0.f;
                bv1 = bias2 ? bias2[c + 1 - splitN] : 0.f;
            }
            int act = firstHalf ? act1 : act2;
#pragma unroll
            for (int half = 0; half < 2; half++) {
                int r = rowBase + warp_m * 64 + mt * 16 + gid + half * 8;
                float v0 = epi_act(acc[mt][nt][half * 2 + 0] + bv0, act);
                float v1 = epi_act(acc[mt][nt][half * 2 + 1] + bv1, act);
                if (firstHalf) {
                    size_t ix = (size_t)r * splitN + c;
                    if (mul) {
                        float2 mm = *(const float2*)(mul + ix);
                        v0 *= mm.x; v1 *= mm.y;
                    }
                    if (C1) {
                        float a0 = v0, a1 = v1;
                        if (addC1) {
                            float2 o = *(const float2*)(C1 + ix);
                            a0 += o.x; a1 += o.y;
                        }
                        float2 w; w.x = a0; w.y = a1;
                        *(float2*)(C1 + ix) = w;
                    }
                    if (C1h) {
                        *reinterpret_cast<__half2*>(C1h + ix) = __floats2half2_rn(v0, v1);
                    }
                } else {
                    size_t ix = (size_t)r * (N - splitN) + (c - splitN);
                    float2 w; w.x = v0; w.y = v1;
                    *(float2*)(C2 + ix) = w;
                }
            }
        }
    }
}

// ===== misc kernels =====
__global__ void embed_kernel(const int* __restrict__ x, const float* __restrict__ emb) {
    int row = blockIdx.x;
    int tok = x[row];
    size_t src = (size_t)tok * Dd, dst = (size_t)row * Dd;
#pragma unroll
    for (int i = 0; i < 4; i++) {
        int c = threadIdx.x + i * 256;
        g_h[dst + c] = emb[src + c];
    }
}

__global__ void __launch_bounds__(256) layernorm_kernel(
    const float* __restrict__ in, const float* __restrict__ in2,
    const float* __restrict__ g, const float* __restrict__ bb,
    float* __restrict__ out, __half* __restrict__ outh)
{
    int row = blockIdx.x;
    size_t base = (size_t)row * Dd;
    float vals[4];
    float s = 0.f, s2 = 0.f;
#pragma unroll
    for (int i = 0; i < 4; i++) {
        int c = threadIdx.x + i * 256;
        float v = in[base + c];
        if (in2) v += in2[base + c];
        vals[i] = v; s += v; s2 += v * v;
    }
    __shared__ float sh1[8], sh2[8];
    s = warpsum(s); s2 = warpsum(s2);
    int w = threadIdx.x >> 5, l = threadIdx.x & 31;
    if (l == 0) { sh1[w] = s; sh2[w] = s2; }
    __syncthreads();
    if (w == 0) {
        float a = (l < 8) ? sh1[l] : 0.f;
        float b2 = (l < 8) ? sh2[l] : 0.f;
        a = warpsum(a); b2 = warpsum(b2);
        if (l == 0) { sh1[0] = a; sh2[0] = b2; }
    }
    __syncthreads();
    float mean = sh1[0] * (1.f / Dd);
    float inv = rsqrtf(sh2[0] * (1.f / Dd) - mean * mean + 1e-5f);
#pragma unroll
    for (int i = 0; i < 4; i++) {
        int c = threadIdx.x + i * 256;
        float v = (vals[i] - mean) * inv * g[c] + bb[c];
        if (out) out[base + c] = v;
        if (outh) outh[base + c] = __float2half_rn(v);
    }
}

// warp-parallel complex scan; writes fp16 ycat directly.
__global__ void __launch_bounds__(256) scan2_kernel(const float* __restrict__ freq) {
    int gwarp = (blockIdx.x * blockDim.x + threadIdx.x) >> 5;
    int lane = threadIdx.x & 31;
    if (gwarp >= Bb * Ff) return;
    int b = gwarp >> 8, f = gwarp & 255;
    float w = 0.1f * freq[f];
    float cw = cosf(w), sw = sinf(w);
    const int L = Tt / 32;
    size_t rbase = (size_t)b * Tt + (size_t)lane * L;

    float Ar = 1.f, Ai = 0.f, Ur = 0.f, Ui = 0.f;
    for (int s = 0; s < L; s++) {
        size_t row = rbase + s;
        float dcy = g_decay[row * Ff + f];
        float ur = g_sp[row * (2 * Ff) + f];
        float ui = g_sp[row * (2 * Ff) + Ff + f];
        float ar = dcy * cw, ai = dcy * sw;
        float nAr = ar * Ar - ai * Ai, nAi = ar * Ai + ai * Ar;
        float nUr = ar * Ur - ai * Ui + ur, nUi = ar * Ui + ai * Ur + ui;
        Ar = nAr; Ai = nAi; Ur = nUr; Ui = nUi;
    }
#pragma unroll
    for (int off = 1; off < 32; off <<= 1) {
        float pAr = __shfl_up_sync(0xffffffffu, Ar, off);
        float pAi = __shfl_up_sync(0xffffffffu, Ai, off);
        float pUr = __shfl_up_sync(0xffffffffu, Ur, off);
        float pUi = __shfl_up_sync(0xffffffffu, Ui, off);
        if (lane >= off) {
            float nAr = Ar * pAr - Ai * pAi;
            float nAi = Ar * pAi + Ai * pAr;
            float nUr = Ar * pUr - Ai * pUi + Ur;
            float nUi = Ar * pUi + Ai * pUr + Ui;
            Ar = nAr; Ai = nAi; Ur = nUr; Ui = nUi;
        }
    }
    float Pr = __shfl_up_sync(0xffffffffu, Ur, 1);
    float Pi = __shfl_up_sync(0xffffffffu, Ui, 1);
    if (lane == 0) { Pr = 0.f; Pi = 0.f; }

    float yr = Pr, yi = Pi;
    for (int s = 0; s < L; s++) {
        size_t row = rbase + s;
        float dcy = g_decay[row * Ff + f];
        float ur = g_sp[row * (2 * Ff) + f];
        float ui = g_sp[row * (2 * Ff) + Ff + f];
        float ar = dcy * cw, ai = dcy * sw;
        float nyr = ar * yr - ai * yi + ur;
        float nyi = ar * yi + ai * yr + ui;
        yr = nyr; yi = nyi;
        a_yc[row * (2 * Ff) + f] = __float2half_rn(yr);
        a_yc[row * (2 * Ff) + Ff + f] = __float2half_rn(yi);
    }
}

__global__ void kl_zero_kernel() { g_accum = 0.f; }
__global__ void __launch_bounds__(256) kl_reduce_kernel() {
    int i = blockIdx.x * blockDim.x + threadIdx.x;
    float v = 0.f;
    if (i < Mrows * LATl) {
        int row = i / LATl, l = i % LATl;
        float mu = g_params[(size_t)row * (2 * LATl) + l];
        float lv = g_params[(size_t)row * (2 * LATl) + LATl + l];
        v = -0.5f * (1.f + lv - mu * mu - expf(lv));
    }
    v = warpsum(v);
    __shared__ float sh[8];
    int w = threadIdx.x >> 5, l = threadIdx.x & 31;
    if (l == 0) sh[w] = v;
    __syncthreads();
    if (w == 0) {
        float a = (l < 8) ? sh[l] : 0.f;
        a = warpsum(a);
        if (l == 0) atomicAdd(&g_accum, a);
    }
}
__global__ void kl_final_kernel(float* __restrict__ out, int do_write) {
    if (do_write) out[0] = 0.01f * fmaxf(g_accum * (1.f / (float)(Mrows * LATl)), 0.05f);
}

// ===== host =====
#define SMEM128 (4 * (128 * ROWB + 128 * ROWB))   // 81920
#define SMEM64  (3 * (64 * ROWB + 128 * ROWB))    // 46080

static void wsplit_f16(const float* in, __half* out, long rows, int K) {
    long n = rows * K;
    split2_f16_kernel<<<(unsigned)((n + 255) / 256), 256>>>(in, out, n, K);
}
static void gemmx(const __half* A, const __half* B,
                  const float* bias1, const float* bias2,
                  int N, int splitN, int Ka, int act1, int act2,
                  const float* mul, float* C1, __half* C1h, int addC1, float* C2) {
    if (N > 1024) {
        dim3 grid(Mrows / 128, N / 128);
        gemm_mma<128><<<grid, 256, SMEM128>>>(A, B, bias1, bias2,
            N, splitN, 2 * Ka, Ka, 2 * Ka, Ka, Ka, act1, act2, mul, C1, C1h, addC1, C2);
    } else {
        dim3 grid(Mrows / 64, N / 128);
        gemm_mma<64><<<grid, 128, SMEM64>>>(A, B, bias1, bias2,
            N, splitN, 2 * Ka, Ka, 2 * Ka, Ka, Ka, act1, act2, mul, C1, C1h, addC1, C2);
    }
}

extern "C" void kernel_launch(void* const* d_in, const int* in_sizes, int n_in,
                              void* d_out, int out_size) {
    (void)in_sizes; (void)n_in;
    const int*   x         = (const int*)  d_in[0];
    const float* emb       = (const float*)d_in[1];
    const float* freq      = (const float*)d_in[2];
    const float* decay_W   = (const float*)d_in[3];
    const float* decay_b   = (const float*)d_in[4];
    const float* spec_in_W = (const float*)d_in[5];
    const float* spec_out_W= (const float*)d_in[6];
    const float* norm1_g   = (const float*)d_in[7];
    const float* norm1_b   = (const float*)d_in[8];
    const float* gate_W    = (const float*)d_in[9];
    const float* gate_b    = (const float*)d_in[10];
    const float* ogate_W   = (const float*)d_in[11];
    const float* ogate_b   = (const float*)d_in[12];
    const float* ffn_g     = (const float*)d_in[13];
    const float* ffn_b     = (const float*)d_in[14];
    const float* ffn_W1    = (const float*)d_in[15];
    const float* ffn_b1    = (const float*)d_in[16];
    const float* ffn_W2    = (const float*)d_in[17];
    const float* ffn_b2    = (const float*)d_in[18];
    const float* vib_g     = (const float*)d_in[19];
    const float* vib_b     = (const float*)d_in[20];
    const float* enc_W     = (const float*)d_in[21];
    const float* enc_b     = (const float*)d_in[22];
    const float* dec_W     = (const float*)d_in[23];
    const float* dec_b     = (const float*)d_in[24];
    const float* normf_g   = (const float*)d_in[25];
    const float* normf_b   = (const float*)d_in[26];
    float* logits = (float*)d_out;

    cudaFuncSetAttribute((const void*)gemm_mma<128>,
                         cudaFuncAttributeMaxDynamicSharedMemorySize, SMEM128);
    cudaFuncSetAttribute((const void*)gemm_mma<64>,
                         cudaFuncAttributeMaxDynamicSharedMemorySize, SMEM64);

    float *p_h, *p_xn, *p_buf1, *p_concept, *p_sp, *p_decay, *p_params;
    cudaGetSymbolAddress((void**)&p_h, g_h);
    cudaGetSymbolAddress((void**)&p_xn, g_xn);
    cudaGetSymbolAddress((void**)&p_buf1, g_buf1);
    cudaGetSymbolAddress((void**)&p_concept, g_concept);
    cudaGetSymbolAddress((void**)&p_sp, g_sp);
    cudaGetSymbolAddress((void**)&p_decay, g_decay);
    cudaGetSymbolAddress((void**)&p_params, g_params);

    __half *pw_go, *pw_dsi, *pw_so, *pw_f1, *pw_f2, *pw_enc, *pw_dec, *pw_emb;
    __half *pa_xnh, *pa_uh, *pa_fh, *pa_muh, *pa_yc;
    cudaGetSymbolAddress((void**)&pw_go, w_go2);
    cudaGetSymbolAddress((void**)&pw_dsi, w_dsi2);
    cudaGetSymbolAddress((void**)&pw_so, w_so2);
    cudaGetSymbolAddress((void**)&pw_f1, w_f12);
    cudaGetSymbolAddress((void**)&pw_f2, w_f22);
    cudaGetSymbolAddress((void**)&pw_enc, w_enc2);
    cudaGetSymbolAddress((void**)&pw_dec, w_dec2);
    cudaGetSymbolAddress((void**)&pw_emb, w_emb2);
    cudaGetSymbolAddress((void**)&pa_xnh, a_xnh);
    cudaGetSymbolAddress((void**)&pa_uh, a_uh);
    cudaGetSymbolAddress((void**)&pa_fh, a_fh);
    cudaGetSymbolAddress((void**)&pa_muh, a_muh);
    cudaGetSymbolAddress((void**)&pa_yc, a_yc);

    // --- launches 0-4 feed the layer-0 fused gate GEMM at launch #5 (ncu -s 5 target) ---
    {
        __half* go0 = pw_go;
        wsplit_f16(gate_W, go0, Dd, Dd);                               // 0
        wsplit_f16(ogate_W, go0 + (size_t)Dd * 2 * Dd, Dd, Dd);        // 1
        embed_kernel<<<Mrows, 256>>>(x, emb);                          // 2
        layernorm_kernel<<<Mrows, 256>>>(p_h, nullptr, norm1_g, norm1_b, p_xn, pa_xnh); // 3
        kl_zero_kernel<<<1, 1>>>();                                    // 4 (independent)
        // 5: fused gate|ogate GEMM — the representative tensor kernel
        gemmx(pa_xnh, go0, gate_b, ogate_b,
              2 * Dd, Dd, Dd, 1, 1, p_xn, nullptr, pa_uh, 0, p_buf1);
    }

    // remaining weight converts
    wsplit_f16(emb, pw_emb, Vv, Dd);
    for (int i = 0; i < NLl; i++) {
        if (i > 0) {
            __half* go = pw_go + (size_t)i * 2 * Dd * 2 * Dd;
            wsplit_f16(gate_W + (size_t)i * Dd * Dd, go, Dd, Dd);
            wsplit_f16(ogate_W + (size_t)i * Dd * Dd, go + (size_t)Dd * 2 * Dd, Dd, Dd);
        }
        __half* dsi = pw_dsi + (size_t)i * 768 * 2 * Dd;
        wsplit_f16(decay_W + (size_t)i * Ff * Dd, dsi, Ff, Dd);
        wsplit_f16(spec_in_W + (size_t)i * 2 * Ff * Dd, dsi + (size_t)Ff * 2 * Dd, 2 * Ff, Dd);
    }
    wsplit_f16(spec_out_W, pw_so, (long)NLl * Dd, 2 * Ff);
    wsplit_f16(ffn_W1, pw_f1, (long)NLl * 4 * Dd, Dd);
    wsplit_f16(ffn_W2, pw_f2, (long)NLl * Dd, 4 * Dd);
    wsplit_f16(enc_W, pw_enc, 2 * LATl, Dd);
    wsplit_f16(dec_W, pw_dec, Dd, LATl);

    for (int i = 0; i < NLl; i++) {
        const __half* goW = pw_go + (size_t)i * 2 * Dd * 2 * Dd;
        const __half* dsiW = pw_dsi + (size_t)i * 768 * 2 * Dd;
        const __half* soW = pw_so + (size_t)i * Dd * 2 * 2 * Ff;
        const __half* w1 = pw_f1 + (size_t)i * 4 * Dd * 2 * Dd;
        const __half* w2 = pw_f2 + (size_t)i * Dd * 2 * 4 * Dd;

        if (i > 0) {
            layernorm_kernel<<<Mrows, 256>>>(p_h, nullptr, norm1_g + i * Dd, norm1_b + i * Dd, p_xn, pa_xnh);
            gemmx(pa_xnh, goW, gate_b + i * Dd, ogate_b + i * Dd,
                  2 * Dd, Dd, Dd, 1, 1, p_xn, nullptr, pa_uh, 0, p_buf1);
        }
        gemmx(pa_uh, dsiW, decay_b + i * Ff, nullptr,
              768, Ff, Dd, 1, 0, nullptr, p_decay, nullptr, 0, p_sp);
        scan2_kernel<<<Bb * Ff * 32 / 256, 256>>>(freq + i * Ff);
        gemmx(pa_yc, soW, nullptr, nullptr,
              Dd, Dd, 2 * Ff, 0, 0, p_buf1, p_h, nullptr, 1, nullptr);
        layernorm_kernel<<<Mrows, 256>>>(p_h, nullptr, ffn_g + i * Dd, ffn_b + i * Dd, nullptr, pa_xnh);
        gemmx(pa_xnh, w1, ffn_b1 + i * 4 * Dd, nullptr,
              4 * Dd, 4 * Dd, Dd, 2, 0, nullptr, nullptr, pa_fh, 0, nullptr);
        gemmx(pa_fh, w2, ffn_b2 + i * Dd, nullptr,
              Dd, Dd, 4 * Dd, 0, 0, nullptr, p_h, nullptr, 1, nullptr);
    }

    // VIB head
    layernorm_kernel<<<Mrows, 256>>>(p_h, nullptr, vib_g, vib_b, nullptr, pa_xnh);
    gemmx(pa_xnh, pw_enc, enc_b, nullptr,
          2 * LATl, 2 * LATl, Dd, 0, 0, nullptr, p_params, nullptr, 0, nullptr);
    cvt_mu_kernel<<<(Mrows * LATl + 255) / 256, 256>>>();
    gemmx(pa_muh, pw_dec, dec_b, nullptr,
          Dd, Dd, LATl, 2, 0, nullptr, p_concept, nullptr, 0, nullptr);
    layernorm_kernel<<<Mrows, 256>>>(p_h, p_concept, normf_g, normf_b, nullptr, pa_xnh);
    gemmx(pa_xnh, pw_emb, nullptr, nullptr,
          Vv, Vv, Dd, 0, 0, nullptr, logits, nullptr, 0, nullptr);

    kl_reduce_kernel<<<(Mrows * LATl + 255) / 256, 256>>>();
    int do_write = (out_size >= Mrows * Vv + 1) ? 1 : 0;
    kl_final_kernel<<<1, 1>>>(logits + (size_t)Mrows * Vv, do_write);
}